// round 1
// baseline (speedup 1.0000x reference)
#include <cuda_runtime.h>

static constexpr int SEQ = 4096;
static constexpr int DM  = 1024;
static constexpr int NH  = 16;
static constexpr int HD  = 64;

// Scratch (allocation-free rule: device globals)
__device__ float g_q[SEQ * DM];
__device__ float g_k[SEQ * DM];
__device__ float g_v[SEQ * DM];
__device__ float g_ctx[SEQ * DM];

// ---------------------------------------------------------------------------
// SGEMM (NT): C[m,n] = sum_k A[m,k] * B[n,k]
// A: [M,K] row-major, B: [N,K] row-major (i.e. y = x @ W^T)
// 128x128 block, BK=8, 8x8 per-thread micro-tile, 256 threads.
// ---------------------------------------------------------------------------
template <int M, int N, int K>
__global__ void __launch_bounds__(256) sgemm_nt(const float* __restrict__ A,
                                                const float* __restrict__ B,
                                                float* __restrict__ C) {
    constexpr int BM = 128, BN = 128, BK = 8;
    __shared__ float As[BK][BM];
    __shared__ float Bs[BK][BN];

    const int tid = threadIdx.x;
    const int tx = tid & 15;
    const int ty = tid >> 4;
    const int bm = blockIdx.y * BM;
    const int bn = blockIdx.x * BN;

    const int lrow = tid >> 1;       // 0..127
    const int lk   = (tid & 1) * 4;  // 0 or 4

    const float* Ap = A + (size_t)(bm + lrow) * K + lk;
    const float* Bp = B + (size_t)(bn + lrow) * K + lk;

    float acc[8][8] = {};

    for (int k0 = 0; k0 < K; k0 += BK) {
        float4 a = *(const float4*)(Ap + k0);
        float4 b = *(const float4*)(Bp + k0);
        __syncthreads();
        As[lk + 0][lrow] = a.x; As[lk + 1][lrow] = a.y;
        As[lk + 2][lrow] = a.z; As[lk + 3][lrow] = a.w;
        Bs[lk + 0][lrow] = b.x; Bs[lk + 1][lrow] = b.y;
        Bs[lk + 2][lrow] = b.z; Bs[lk + 3][lrow] = b.w;
        __syncthreads();

#pragma unroll
        for (int kk = 0; kk < BK; ++kk) {
            float4 a0 = *(const float4*)&As[kk][ty * 8];
            float4 a1 = *(const float4*)&As[kk][ty * 8 + 4];
            float4 b0 = *(const float4*)&Bs[kk][tx * 8];
            float4 b1 = *(const float4*)&Bs[kk][tx * 8 + 4];
            float ar[8] = {a0.x, a0.y, a0.z, a0.w, a1.x, a1.y, a1.z, a1.w};
            float br[8] = {b0.x, b0.y, b0.z, b0.w, b1.x, b1.y, b1.z, b1.w};
#pragma unroll
            for (int i = 0; i < 8; ++i)
#pragma unroll
                for (int j = 0; j < 8; ++j)
                    acc[i][j] += ar[i] * br[j];
        }
    }

#pragma unroll
    for (int i = 0; i < 8; ++i) {
        float* Cp = C + (size_t)(bm + ty * 8 + i) * N + bn + tx * 8;
        float4 c0 = make_float4(acc[i][0], acc[i][1], acc[i][2], acc[i][3]);
        float4 c1 = make_float4(acc[i][4], acc[i][5], acc[i][6], acc[i][7]);
        *(float4*)(Cp)     = c0;
        *(float4*)(Cp + 4) = c1;
    }
}

// ---------------------------------------------------------------------------
// Fused causal flash attention, fp32.
// Grid: (SEQ/64, NH). Block: 256 threads (16x16), each thread owns a 4x4 tile.
// Layouts (all 64x64 fp32 tiles, 48 KB static smem total):
//   Qs : Q^T with float4-slot XOR swizzle  (Qs[d][swz(c= i/4, d)*4 + i%4])
//   KVs: K phase -> K^T swizzled like Qs;  V phase -> natural [j][d]
//   Ps : probabilities, natural [i][j]
// Swizzle slot(c,d) = c ^ ((d>>2)&15): conflict-free for both the transpose
// stores (lanes vary d/4) and the fragment loads (lanes vary c).
// ---------------------------------------------------------------------------
__global__ void __launch_bounds__(256) attn_kernel(const float* __restrict__ Q,
                                                   const float* __restrict__ K,
                                                   const float* __restrict__ V,
                                                   float* __restrict__ O) {
    __shared__ float Qs[64][64];
    __shared__ float KVs[64][64];
    __shared__ float Ps[64][64];

    const int tid = threadIdx.x;
    const int tx = tid & 15;
    const int ty = tid >> 4;
    const int head = blockIdx.y;
    const int qt = blockIdx.x;
    const int qrow0 = qt * 64;
    const int col0 = head * HD;
    const float scale = 0.125f;  // 1/sqrt(64)

    // ---- Load Q tile: transposed + swizzled + pre-scaled (once) ----
    for (int e = tid; e < 64 * 64; e += 256) {
        int i = e >> 6;
        int d = e & 63;
        float val = Q[(size_t)(qrow0 + i) * DM + col0 + d] * scale;
        int cp = (i >> 2) ^ ((d >> 2) & 15);
        Qs[d][cp * 4 + (i & 3)] = val;
    }

    float m_r[4], l_r[4], o_acc[4][4];
#pragma unroll
    for (int r = 0; r < 4; ++r) {
        m_r[r] = -1e30f;
        l_r[r] = 0.0f;
#pragma unroll
        for (int c = 0; c < 4; ++c) o_acc[r][c] = 0.0f;
    }

    const int nkb = qt + 1;  // causal: only kv blocks <= q block
    for (int kb = 0; kb < nkb; ++kb) {
        __syncthreads();  // prev iter done reading KVs (as V) and Ps

        // ---- Load K tile: transposed + swizzled ----
        {
            const int dbase = (tid & 15) * 4;
#pragma unroll
            for (int p = 0; p < 4; ++p) {
                int j = (tid >> 4) + p * 16;
                float4 kv = *(const float4*)&K[(size_t)(kb * 64 + j) * DM + col0 + dbase];
                float vals[4] = {kv.x, kv.y, kv.z, kv.w};
#pragma unroll
                for (int q = 0; q < 4; ++q) {
                    int d = dbase + q;
                    int cp = (j >> 2) ^ ((d >> 2) & 15);
                    KVs[d][cp * 4 + (j & 3)] = vals[q];
                }
            }
        }
        __syncthreads();

        // ---- S = Q K^T (64x64x64), thread computes 4x4 ----
        float s[4][4] = {};
#pragma unroll 8
        for (int d = 0; d < 64; ++d) {
            int sw = (d >> 2) & 15;
            float4 qv = *(const float4*)&Qs[d][(ty ^ sw) * 4];
            float4 kv = *(const float4*)&KVs[d][(tx ^ sw) * 4];
            float qa[4] = {qv.x, qv.y, qv.z, qv.w};
            float ka[4] = {kv.x, kv.y, kv.z, kv.w};
#pragma unroll
            for (int r = 0; r < 4; ++r)
#pragma unroll
                for (int c = 0; c < 4; ++c)
                    s[r][c] += qa[r] * ka[c];
        }

        // ---- Causal mask on diagonal block (matches reference: -10000) ----
        if (kb == qt) {
#pragma unroll
            for (int r = 0; r < 4; ++r) {
                int qi = 4 * ty + r;
#pragma unroll
                for (int c = 0; c < 4; ++c) {
                    int kj = 4 * tx + c;
                    if (kj > qi) s[r][c] = -10000.0f;
                }
            }
        }

        // ---- Online softmax ----
        float rowmax[4], rowsum[4], corr[4];
#pragma unroll
        for (int r = 0; r < 4; ++r) {
            float mx = fmaxf(fmaxf(s[r][0], s[r][1]), fmaxf(s[r][2], s[r][3]));
#pragma unroll
            for (int off = 8; off >= 1; off >>= 1)
                mx = fmaxf(mx, __shfl_xor_sync(0xffffffffu, mx, off, 16));
            rowmax[r] = mx;
        }
#pragma unroll
        for (int r = 0; r < 4; ++r) {
            float mnew = fmaxf(m_r[r], rowmax[r]);
            corr[r] = __expf(m_r[r] - mnew);
            m_r[r] = mnew;
            float rs = 0.0f;
#pragma unroll
            for (int c = 0; c < 4; ++c) {
                float p = __expf(s[r][c] - mnew);
                s[r][c] = p;
                rs += p;
            }
            rowsum[r] = rs;
        }
#pragma unroll
        for (int r = 0; r < 4; ++r) {
#pragma unroll
            for (int off = 8; off >= 1; off >>= 1)
                rowsum[r] += __shfl_xor_sync(0xffffffffu, rowsum[r], off, 16);
            l_r[r] = l_r[r] * corr[r] + rowsum[r];
#pragma unroll
            for (int c = 0; c < 4; ++c) o_acc[r][c] *= corr[r];
        }

        // ---- Write P (natural layout, float4 along j: conflict-free) ----
#pragma unroll
        for (int r = 0; r < 4; ++r) {
            float4 pv = make_float4(s[r][0], s[r][1], s[r][2], s[r][3]);
            *(float4*)&Ps[4 * ty + r][4 * tx] = pv;
        }
        __syncthreads();  // Ps complete; all QK reads of KVs done

        // ---- Load V tile (natural [j][d]) into KVs ----
        {
            const int dbase = (tid & 15) * 4;
#pragma unroll
            for (int p = 0; p < 4; ++p) {
                int j = (tid >> 4) + p * 16;
                float4 vv = *(const float4*)&V[(size_t)(kb * 64 + j) * DM + col0 + dbase];
                *(float4*)&KVs[j][dbase] = vv;
            }
        }
        __syncthreads();

        // ---- O += P V (64x64x64), thread computes rows 4ty.., cols 4tx.. ----
#pragma unroll 4
        for (int j4 = 0; j4 < 64; j4 += 4) {
            float pa[4][4];
#pragma unroll
            for (int r = 0; r < 4; ++r) {
                float4 pv = *(const float4*)&Ps[4 * ty + r][j4];
                pa[r][0] = pv.x; pa[r][1] = pv.y; pa[r][2] = pv.z; pa[r][3] = pv.w;
            }
#pragma unroll
            for (int jj = 0; jj < 4; ++jj) {
                float4 vv = *(const float4*)&KVs[j4 + jj][4 * tx];
                float va[4] = {vv.x, vv.y, vv.z, vv.w};
#pragma unroll
                for (int r = 0; r < 4; ++r)
#pragma unroll
                    for (int c = 0; c < 4; ++c)
                        o_acc[r][c] += pa[r][jj] * va[c];
            }
        }
    }

    // ---- Finalize: divide by l, write ctx ----
#pragma unroll
    for (int r = 0; r < 4; ++r) {
        float inv = 1.0f / l_r[r];
        float4 ov = make_float4(o_acc[r][0] * inv, o_acc[r][1] * inv,
                                o_acc[r][2] * inv, o_acc[r][3] * inv);
        *(float4*)&O[(size_t)(qrow0 + 4 * ty + r) * DM + col0 + 4 * tx] = ov;
    }
}

// ---------------------------------------------------------------------------
extern "C" void kernel_launch(void* const* d_in, const int* in_sizes, int n_in,
                              void* d_out, int out_size) {
    const float* x  = (const float*)d_in[0];
    const float* wq = (const float*)d_in[1];
    const float* wk = (const float*)d_in[2];
    const float* wv = (const float*)d_in[3];
    const float* wo = (const float*)d_in[4];
    float* out = (float*)d_out;

    float *q, *k, *v, *ctx;
    cudaGetSymbolAddress((void**)&q,   g_q);
    cudaGetSymbolAddress((void**)&k,   g_k);
    cudaGetSymbolAddress((void**)&v,   g_v);
    cudaGetSymbolAddress((void**)&ctx, g_ctx);

    dim3 gemm_grid(DM / 128, SEQ / 128);
    sgemm_nt<SEQ, DM, DM><<<gemm_grid, 256>>>(x, wq, q);
    sgemm_nt<SEQ, DM, DM><<<gemm_grid, 256>>>(x, wk, k);
    sgemm_nt<SEQ, DM, DM><<<gemm_grid, 256>>>(x, wv, v);

    attn_kernel<<<dim3(SEQ / 64, NH), 256>>>(q, k, v, ctx);

    sgemm_nt<SEQ, DM, DM><<<gemm_grid, 256>>>(ctx, wo, out);
}

// round 2
// speedup vs baseline: 1.3054x; 1.3054x over previous
#include <cuda_runtime.h>
#include <cstdint>

static constexpr int SEQ = 4096;
static constexpr int DM  = 1024;
static constexpr int NH  = 16;
static constexpr int HD  = 64;

// Scratch (allocation-free rule: device globals)
__device__ float g_q[SEQ * DM];
__device__ float g_k[SEQ * DM];
__device__ float g_v[SEQ * DM];
__device__ float g_ctx[SEQ * DM];

// ---------------------------------------------------------------------------
// TF32 tensor-core GEMM (NT): C[m,n] = sum_k A[m,k] * B[n,k]
// A: [M,K] row-major, B: [N,K] row-major  (y = x @ W^T)
// Block 128x128, BK=16, 8 warps in 2(M) x 4(N), warp tile 64x32.
// mma.sync.aligned.m16n8k8.row.col.f32.tf32.tf32.f32
// Smem tiles [128][20] (pad 16->20) => fragment LDS fully conflict-free.
// ---------------------------------------------------------------------------
__device__ __forceinline__ uint32_t f2tf32(float f) {
    uint32_t u;
    asm("cvt.rna.tf32.f32 %0, %1;" : "=r"(u) : "f"(f));
    return u;
}

__device__ __forceinline__ void mma_tf32(float* d, const uint32_t* a, const uint32_t* b) {
    asm volatile(
        "mma.sync.aligned.m16n8k8.row.col.f32.tf32.tf32.f32 "
        "{%0,%1,%2,%3}, {%4,%5,%6,%7}, {%8,%9}, {%0,%1,%2,%3};"
        : "+f"(d[0]), "+f"(d[1]), "+f"(d[2]), "+f"(d[3])
        : "r"(a[0]), "r"(a[1]), "r"(a[2]), "r"(a[3]), "r"(b[0]), "r"(b[1]));
}

template <int M, int N, int K>
__global__ void __launch_bounds__(256) gemm_tf32_nt(const float* __restrict__ A,
                                                    const float* __restrict__ B,
                                                    float* __restrict__ C) {
    constexpr int BM = 128, BN = 128, BK = 16;
    constexpr int PAD = 20;
    __shared__ uint32_t As[BM][PAD];
    __shared__ uint32_t Bs[BN][PAD];

    const int tid  = threadIdx.x;
    const int warp = tid >> 5;
    const int lane = tid & 31;
    const int grp  = lane >> 2;   // 0..7
    const int lq   = lane & 3;    // 0..3

    const int warp_m = warp & 1;   // 0..1
    const int warp_n = warp >> 1;  // 0..3
    const int wm0 = warp_m * 64;
    const int wn0 = warp_n * 32;

    const int bm = blockIdx.y * BM;
    const int bn = blockIdx.x * BN;

    // gmem staging map: thread -> (row = tid>>1, khalf = (tid&1)*8)
    const int lrow = tid >> 1;
    const int lkh  = (tid & 1) * 8;
    const float* Ap = A + (size_t)(bm + lrow) * K + lkh;
    const float* Bp = B + (size_t)(bn + lrow) * K + lkh;

    float acc[4][4][4] = {};  // [m-tile][n-tile][frag]

    // prefetch first tile into registers
    float4 ra0 = *(const float4*)(Ap);
    float4 ra1 = *(const float4*)(Ap + 4);
    float4 rb0 = *(const float4*)(Bp);
    float4 rb1 = *(const float4*)(Bp + 4);

    for (int k0 = 0; k0 < K; k0 += BK) {
        // stage registers -> smem (tf32)
        {
            uint4 ua0 = make_uint4(f2tf32(ra0.x), f2tf32(ra0.y), f2tf32(ra0.z), f2tf32(ra0.w));
            uint4 ua1 = make_uint4(f2tf32(ra1.x), f2tf32(ra1.y), f2tf32(ra1.z), f2tf32(ra1.w));
            uint4 ub0 = make_uint4(f2tf32(rb0.x), f2tf32(rb0.y), f2tf32(rb0.z), f2tf32(rb0.w));
            uint4 ub1 = make_uint4(f2tf32(rb1.x), f2tf32(rb1.y), f2tf32(rb1.z), f2tf32(rb1.w));
            *(uint4*)&As[lrow][lkh]     = ua0;
            *(uint4*)&As[lrow][lkh + 4] = ua1;
            *(uint4*)&Bs[lrow][lkh]     = ub0;
            *(uint4*)&Bs[lrow][lkh + 4] = ub1;
        }
        __syncthreads();

        // prefetch next tile (overlaps with MMA below)
        if (k0 + BK < K) {
            ra0 = *(const float4*)(Ap + k0 + BK);
            ra1 = *(const float4*)(Ap + k0 + BK + 4);
            rb0 = *(const float4*)(Bp + k0 + BK);
            rb1 = *(const float4*)(Bp + k0 + BK + 4);
        }

#pragma unroll
        for (int ks = 0; ks < BK; ks += 8) {
            uint32_t afr[4][4];
            uint32_t bfr[4][2];
#pragma unroll
            for (int im = 0; im < 4; ++im) {
                int r0 = wm0 + im * 16;
                afr[im][0] = As[r0 + grp][ks + lq];
                afr[im][1] = As[r0 + grp + 8][ks + lq];
                afr[im][2] = As[r0 + grp][ks + lq + 4];
                afr[im][3] = As[r0 + grp + 8][ks + lq + 4];
            }
#pragma unroll
            for (int in = 0; in < 4; ++in) {
                int c0 = wn0 + in * 8;
                bfr[in][0] = Bs[c0 + grp][ks + lq];
                bfr[in][1] = Bs[c0 + grp][ks + lq + 4];
            }
#pragma unroll
            for (int im = 0; im < 4; ++im)
#pragma unroll
                for (int in = 0; in < 4; ++in)
                    mma_tf32(acc[im][in], afr[im], bfr[in]);
        }
        __syncthreads();
    }

    // epilogue: d0,d1 at (row=grp, col=2lq..2lq+1); d2,d3 at row=grp+8
#pragma unroll
    for (int im = 0; im < 4; ++im) {
#pragma unroll
        for (int in = 0; in < 4; ++in) {
            size_t row0 = (size_t)(bm + wm0 + im * 16 + grp);
            int col = bn + wn0 + in * 8 + 2 * lq;
            float2 v01 = make_float2(acc[im][in][0], acc[im][in][1]);
            float2 v23 = make_float2(acc[im][in][2], acc[im][in][3]);
            *(float2*)&C[row0 * N + col]       = v01;
            *(float2*)&C[(row0 + 8) * N + col] = v23;
        }
    }
}

// ---------------------------------------------------------------------------
// Fused causal flash attention, fp32 (unchanged from passing round 1).
// ---------------------------------------------------------------------------
__global__ void __launch_bounds__(256) attn_kernel(const float* __restrict__ Q,
                                                   const float* __restrict__ K,
                                                   const float* __restrict__ V,
                                                   float* __restrict__ O) {
    __shared__ float Qs[64][64];
    __shared__ float KVs[64][64];
    __shared__ float Ps[64][64];

    const int tid = threadIdx.x;
    const int tx = tid & 15;
    const int ty = tid >> 4;
    const int head = blockIdx.y;
    const int qt = blockIdx.x;
    const int qrow0 = qt * 64;
    const int col0 = head * HD;
    const float scale = 0.125f;  // 1/sqrt(64)

    for (int e = tid; e < 64 * 64; e += 256) {
        int i = e >> 6;
        int d = e & 63;
        float val = Q[(size_t)(qrow0 + i) * DM + col0 + d] * scale;
        int cp = (i >> 2) ^ ((d >> 2) & 15);
        Qs[d][cp * 4 + (i & 3)] = val;
    }

    float m_r[4], l_r[4], o_acc[4][4];
#pragma unroll
    for (int r = 0; r < 4; ++r) {
        m_r[r] = -1e30f;
        l_r[r] = 0.0f;
#pragma unroll
        for (int c = 0; c < 4; ++c) o_acc[r][c] = 0.0f;
    }

    const int nkb = qt + 1;
    for (int kb = 0; kb < nkb; ++kb) {
        __syncthreads();

        {
            const int dbase = (tid & 15) * 4;
#pragma unroll
            for (int p = 0; p < 4; ++p) {
                int j = (tid >> 4) + p * 16;
                float4 kv = *(const float4*)&K[(size_t)(kb * 64 + j) * DM + col0 + dbase];
                float vals[4] = {kv.x, kv.y, kv.z, kv.w};
#pragma unroll
                for (int q = 0; q < 4; ++q) {
                    int d = dbase + q;
                    int cp = (j >> 2) ^ ((d >> 2) & 15);
                    KVs[d][cp * 4 + (j & 3)] = vals[q];
                }
            }
        }
        __syncthreads();

        float s[4][4] = {};
#pragma unroll 8
        for (int d = 0; d < 64; ++d) {
            int sw = (d >> 2) & 15;
            float4 qv = *(const float4*)&Qs[d][(ty ^ sw) * 4];
            float4 kv = *(const float4*)&KVs[d][(tx ^ sw) * 4];
            float qa[4] = {qv.x, qv.y, qv.z, qv.w};
            float ka[4] = {kv.x, kv.y, kv.z, kv.w};
#pragma unroll
            for (int r = 0; r < 4; ++r)
#pragma unroll
                for (int c = 0; c < 4; ++c)
                    s[r][c] += qa[r] * ka[c];
        }

        if (kb == qt) {
#pragma unroll
            for (int r = 0; r < 4; ++r) {
                int qi = 4 * ty + r;
#pragma unroll
                for (int c = 0; c < 4; ++c) {
                    int kj = 4 * tx + c;
                    if (kj > qi) s[r][c] = -10000.0f;
                }
            }
        }

        float rowmax[4], rowsum[4], corr[4];
#pragma unroll
        for (int r = 0; r < 4; ++r) {
            float mx = fmaxf(fmaxf(s[r][0], s[r][1]), fmaxf(s[r][2], s[r][3]));
#pragma unroll
            for (int off = 8; off >= 1; off >>= 1)
                mx = fmaxf(mx, __shfl_xor_sync(0xffffffffu, mx, off, 16));
            rowmax[r] = mx;
        }
#pragma unroll
        for (int r = 0; r < 4; ++r) {
            float mnew = fmaxf(m_r[r], rowmax[r]);
            corr[r] = __expf(m_r[r] - mnew);
            m_r[r] = mnew;
            float rs = 0.0f;
#pragma unroll
            for (int c = 0; c < 4; ++c) {
                float p = __expf(s[r][c] - mnew);
                s[r][c] = p;
                rs += p;
            }
            rowsum[r] = rs;
        }
#pragma unroll
        for (int r = 0; r < 4; ++r) {
#pragma unroll
            for (int off = 8; off >= 1; off >>= 1)
                rowsum[r] += __shfl_xor_sync(0xffffffffu, rowsum[r], off, 16);
            l_r[r] = l_r[r] * corr[r] + rowsum[r];
#pragma unroll
            for (int c = 0; c < 4; ++c) o_acc[r][c] *= corr[r];
        }

#pragma unroll
        for (int r = 0; r < 4; ++r) {
            float4 pv = make_float4(s[r][0], s[r][1], s[r][2], s[r][3]);
            *(float4*)&Ps[4 * ty + r][4 * tx] = pv;
        }
        __syncthreads();

        {
            const int dbase = (tid & 15) * 4;
#pragma unroll
            for (int p = 0; p < 4; ++p) {
                int j = (tid >> 4) + p * 16;
                float4 vv = *(const float4*)&V[(size_t)(kb * 64 + j) * DM + col0 + dbase];
                *(float4*)&KVs[j][dbase] = vv;
            }
        }
        __syncthreads();

#pragma unroll 4
        for (int j4 = 0; j4 < 64; j4 += 4) {
            float pa[4][4];
#pragma unroll
            for (int r = 0; r < 4; ++r) {
                float4 pv = *(const float4*)&Ps[4 * ty + r][j4];
                pa[r][0] = pv.x; pa[r][1] = pv.y; pa[r][2] = pv.z; pa[r][3] = pv.w;
            }
#pragma unroll
            for (int jj = 0; jj < 4; ++jj) {
                float4 vv = *(const float4*)&KVs[j4 + jj][4 * tx];
                float va[4] = {vv.x, vv.y, vv.z, vv.w};
#pragma unroll
                for (int r = 0; r < 4; ++r)
#pragma unroll
                    for (int c = 0; c < 4; ++c)
                        o_acc[r][c] += pa[r][jj] * va[c];
            }
        }
    }

#pragma unroll
    for (int r = 0; r < 4; ++r) {
        float inv = 1.0f / l_r[r];
        float4 ov = make_float4(o_acc[r][0] * inv, o_acc[r][1] * inv,
                                o_acc[r][2] * inv, o_acc[r][3] * inv);
        *(float4*)&O[(size_t)(qrow0 + 4 * ty + r) * DM + col0 + 4 * tx] = ov;
    }
}

// ---------------------------------------------------------------------------
extern "C" void kernel_launch(void* const* d_in, const int* in_sizes, int n_in,
                              void* d_out, int out_size) {
    const float* x  = (const float*)d_in[0];
    const float* wq = (const float*)d_in[1];
    const float* wk = (const float*)d_in[2];
    const float* wv = (const float*)d_in[3];
    const float* wo = (const float*)d_in[4];
    float* out = (float*)d_out;

    float *q, *k, *v, *ctx;
    cudaGetSymbolAddress((void**)&q,   g_q);
    cudaGetSymbolAddress((void**)&k,   g_k);
    cudaGetSymbolAddress((void**)&v,   g_v);
    cudaGetSymbolAddress((void**)&ctx, g_ctx);

    dim3 gemm_grid(DM / 128, SEQ / 128);
    gemm_tf32_nt<SEQ, DM, DM><<<gemm_grid, 256>>>(x, wq, q);
    gemm_tf32_nt<SEQ, DM, DM><<<gemm_grid, 256>>>(x, wk, k);
    gemm_tf32_nt<SEQ, DM, DM><<<gemm_grid, 256>>>(x, wv, v);

    attn_kernel<<<dim3(SEQ / 64, NH), 256>>>(q, k, v, ctx);

    gemm_tf32_nt<SEQ, DM, DM><<<gemm_grid, 256>>>(ctx, wo, out);
}

// round 3
// speedup vs baseline: 2.1513x; 1.6480x over previous
#include <cuda_runtime.h>
#include <cstdint>

static constexpr int SEQ = 4096;
static constexpr int DM  = 1024;
static constexpr int NH  = 16;
static constexpr int HD  = 64;

// Scratch (allocation-free rule: device globals)
__device__ float g_q[SEQ * DM];
__device__ float g_k[SEQ * DM];
__device__ float g_v[SEQ * DM];
__device__ float g_ctx[SEQ * DM];

__device__ __forceinline__ uint32_t f2tf32(float f) {
    uint32_t u;
    asm("cvt.rna.tf32.f32 %0, %1;" : "=r"(u) : "f"(f));
    return u;
}

__device__ __forceinline__ void mma_tf32(float* d, const uint32_t* a, const uint32_t* b) {
    asm volatile(
        "mma.sync.aligned.m16n8k8.row.col.f32.tf32.tf32.f32 "
        "{%0,%1,%2,%3}, {%4,%5,%6,%7}, {%8,%9}, {%0,%1,%2,%3};"
        : "+f"(d[0]), "+f"(d[1]), "+f"(d[2]), "+f"(d[3])
        : "r"(a[0]), "r"(a[1]), "r"(a[2]), "r"(a[3]), "r"(b[0]), "r"(b[1]));
}

// ---------------------------------------------------------------------------
// TF32 tensor-core GEMM (NT): C[m,n] = sum_k A[m,k] * B[n,k]   (unchanged R2)
// ---------------------------------------------------------------------------
template <int M, int N, int K>
__global__ void __launch_bounds__(256) gemm_tf32_nt(const float* __restrict__ A,
                                                    const float* __restrict__ B,
                                                    float* __restrict__ C) {
    constexpr int BM = 128, BN = 128, BK = 16;
    constexpr int PAD = 20;
    __shared__ uint32_t As[BM][PAD];
    __shared__ uint32_t Bs[BN][PAD];

    const int tid  = threadIdx.x;
    const int warp = tid >> 5;
    const int lane = tid & 31;
    const int grp  = lane >> 2;
    const int lq   = lane & 3;

    const int warp_m = warp & 1;
    const int warp_n = warp >> 1;
    const int wm0 = warp_m * 64;
    const int wn0 = warp_n * 32;

    const int bm = blockIdx.y * BM;
    const int bn = blockIdx.x * BN;

    const int lrow = tid >> 1;
    const int lkh  = (tid & 1) * 8;
    const float* Ap = A + (size_t)(bm + lrow) * K + lkh;
    const float* Bp = B + (size_t)(bn + lrow) * K + lkh;

    float acc[4][4][4] = {};

    float4 ra0 = *(const float4*)(Ap);
    float4 ra1 = *(const float4*)(Ap + 4);
    float4 rb0 = *(const float4*)(Bp);
    float4 rb1 = *(const float4*)(Bp + 4);

    for (int k0 = 0; k0 < K; k0 += BK) {
        {
            uint4 ua0 = make_uint4(f2tf32(ra0.x), f2tf32(ra0.y), f2tf32(ra0.z), f2tf32(ra0.w));
            uint4 ua1 = make_uint4(f2tf32(ra1.x), f2tf32(ra1.y), f2tf32(ra1.z), f2tf32(ra1.w));
            uint4 ub0 = make_uint4(f2tf32(rb0.x), f2tf32(rb0.y), f2tf32(rb0.z), f2tf32(rb0.w));
            uint4 ub1 = make_uint4(f2tf32(rb1.x), f2tf32(rb1.y), f2tf32(rb1.z), f2tf32(rb1.w));
            *(uint4*)&As[lrow][lkh]     = ua0;
            *(uint4*)&As[lrow][lkh + 4] = ua1;
            *(uint4*)&Bs[lrow][lkh]     = ub0;
            *(uint4*)&Bs[lrow][lkh + 4] = ub1;
        }
        __syncthreads();

        if (k0 + BK < K) {
            ra0 = *(const float4*)(Ap + k0 + BK);
            ra1 = *(const float4*)(Ap + k0 + BK + 4);
            rb0 = *(const float4*)(Bp + k0 + BK);
            rb1 = *(const float4*)(Bp + k0 + BK + 4);
        }

#pragma unroll
        for (int ks = 0; ks < BK; ks += 8) {
            uint32_t afr[4][4];
            uint32_t bfr[4][2];
#pragma unroll
            for (int im = 0; im < 4; ++im) {
                int r0 = wm0 + im * 16;
                afr[im][0] = As[r0 + grp][ks + lq];
                afr[im][1] = As[r0 + grp + 8][ks + lq];
                afr[im][2] = As[r0 + grp][ks + lq + 4];
                afr[im][3] = As[r0 + grp + 8][ks + lq + 4];
            }
#pragma unroll
            for (int in = 0; in < 4; ++in) {
                int c0 = wn0 + in * 8;
                bfr[in][0] = Bs[c0 + grp][ks + lq];
                bfr[in][1] = Bs[c0 + grp][ks + lq + 4];
            }
#pragma unroll
            for (int im = 0; im < 4; ++im)
#pragma unroll
                for (int in = 0; in < 4; ++in)
                    mma_tf32(acc[im][in], afr[im], bfr[in]);
        }
        __syncthreads();
    }

#pragma unroll
    for (int im = 0; im < 4; ++im) {
#pragma unroll
        for (int in = 0; in < 4; ++in) {
            size_t row0 = (size_t)(bm + wm0 + im * 16 + grp);
            int col = bn + wn0 + in * 8 + 2 * lq;
            *(float2*)&C[row0 * N + col]       = make_float2(acc[im][in][0], acc[im][in][1]);
            *(float2*)&C[(row0 + 8) * N + col] = make_float2(acc[im][in][2], acc[im][in][3]);
        }
    }
}

// ---------------------------------------------------------------------------
// Flash attention with TF32 MMA. q-tile 128, kv-tile 64, 4 warps x m32.
// Dynamic smem layout (stride 68 words per row):
//   Qs[128][68]  Q tile, pre-scaled, tf32          (A-operand, [m][k])
//   Ks[64][68]   K tile, tf32                      (B-operand, [n][k])
//   Vt[64][68]   V^T tile, tf32, bit5-XOR swizzle  (B-operand, [n=d][k=j])
//   Ps[128][68]  probabilities, tf32               (A-operand, [m][k=j])
// ---------------------------------------------------------------------------
static constexpr int ATT_SMEM_WORDS = (128 + 64 + 64 + 128) * 68;
static constexpr int ATT_SMEM_BYTES = ATT_SMEM_WORDS * 4;

__global__ void __launch_bounds__(128) attn_mma(const float* __restrict__ Q,
                                                const float* __restrict__ K,
                                                const float* __restrict__ V,
                                                float* __restrict__ O) {
    extern __shared__ uint32_t sm[];
    uint32_t* Qs = sm;                   // [128][68]
    uint32_t* Ks = Qs + 128 * 68;        // [64][68]
    uint32_t* Vt = Ks + 64 * 68;         // [64][68]
    uint32_t* Ps = Vt + 64 * 68;         // [128][68]

    const int tid  = threadIdx.x;
    const int warp = tid >> 5;
    const int lane = tid & 31;
    const int grp  = lane >> 2;
    const int lq   = lane & 3;
    const int head = blockIdx.y;
    const int qt   = (int)gridDim.x - 1 - (int)blockIdx.x;  // long CTAs first
    const int qrow0 = qt * 128;
    const int col0  = head * HD;
    const int w32   = warp * 32;

    // ---- Load Q tile (128x64), scale by 1/8, convert tf32 ----
    for (int idx = tid; idx < 128 * 16; idx += 128) {
        int row = idx >> 4;
        int p4  = (idx & 15) * 4;
        float4 qv = *(const float4*)&Q[(size_t)(qrow0 + row) * DM + col0 + p4];
        uint4 u = make_uint4(f2tf32(qv.x * 0.125f), f2tf32(qv.y * 0.125f),
                             f2tf32(qv.z * 0.125f), f2tf32(qv.w * 0.125f));
        *(uint4*)&Qs[row * 68 + p4] = u;
    }

    float Oa[2][8][4];
    float m_s[4], l_s[4];
#pragma unroll
    for (int h = 0; h < 2; ++h)
#pragma unroll
        for (int nt = 0; nt < 8; ++nt)
#pragma unroll
            for (int c = 0; c < 4; ++c) Oa[h][nt][c] = 0.0f;
#pragma unroll
    for (int r = 0; r < 4; ++r) { m_s[r] = -1e30f; l_s[r] = 0.0f; }

    // staging map for K/V: 2 threads per kv row
    const int sj   = tid >> 1;          // kv row 0..63
    const int soff = (tid & 1) * 32;    // col half
    const int ssw  = (tid & 1) << 4;    // bit5(d) XOR for Vt

    const int nkb = 2 * qt + 2;
    for (int kb = 0; kb < nkb; ++kb) {
        __syncthreads();  // prev iter finished reading Ks/Vt

        // ---- Stage K (natural [j][d]) and V^T (swizzled [d][j]) ----
        {
            const float* Kp = K + (size_t)(kb * 64 + sj) * DM + col0 + soff;
            const float* Vp = V + (size_t)(kb * 64 + sj) * DM + col0 + soff;
#pragma unroll
            for (int p = 0; p < 8; ++p) {
                float4 kv = *(const float4*)(Kp + p * 4);
                *(uint4*)&Ks[sj * 68 + soff + p * 4] =
                    make_uint4(f2tf32(kv.x), f2tf32(kv.y), f2tf32(kv.z), f2tf32(kv.w));
                float4 vv = *(const float4*)(Vp + p * 4);
                int d = soff + p * 4;
                int jx = sj ^ ssw;
                Vt[(d + 0) * 68 + jx] = f2tf32(vv.x);
                Vt[(d + 1) * 68 + jx] = f2tf32(vv.y);
                Vt[(d + 2) * 68 + jx] = f2tf32(vv.z);
                Vt[(d + 3) * 68 + jx] = f2tf32(vv.w);
            }
        }
        __syncthreads();

        // ---- S = Q K^T : m32 x n64 x k64 per warp ----
        float S[2][8][4];
#pragma unroll
        for (int h = 0; h < 2; ++h)
#pragma unroll
            for (int nt = 0; nt < 8; ++nt)
#pragma unroll
                for (int c = 0; c < 4; ++c) S[h][nt][c] = 0.0f;

#pragma unroll
        for (int kt = 0; kt < 8; ++kt) {
            const int kc = kt * 8;
            uint32_t a[2][4];
#pragma unroll
            for (int h = 0; h < 2; ++h) {
                int r = (w32 + h * 16 + grp) * 68 + kc + lq;
                a[h][0] = Qs[r];
                a[h][1] = Qs[r + 8 * 68];
                a[h][2] = Qs[r + 4];
                a[h][3] = Qs[r + 8 * 68 + 4];
            }
#pragma unroll
            for (int nt = 0; nt < 8; ++nt) {
                uint32_t b[2];
                int o = (nt * 8 + grp) * 68 + kc + lq;
                b[0] = Ks[o];
                b[1] = Ks[o + 4];
                mma_tf32(S[0][nt], a[0], b);
                mma_tf32(S[1][nt], a[1], b);
            }
        }

        // ---- Causal mask (only last two kv blocks need it) ----
        if (kb >= 2 * qt) {
#pragma unroll
            for (int h = 0; h < 2; ++h)
#pragma unroll
                for (int nt = 0; nt < 8; ++nt)
#pragma unroll
                    for (int c = 0; c < 4; ++c) {
                        int qi = qrow0 + w32 + h * 16 + grp + ((c >> 1) << 3);
                        int kj = kb * 64 + nt * 8 + 2 * lq + (c & 1);
                        if (kj > qi) S[h][nt][c] = -10000.0f;
                    }
        }

        // ---- Online softmax (4 row-slots per thread) ----
#pragma unroll
        for (int rs = 0; rs < 4; ++rs) {
            const int h = rs >> 1;
            const int off = (rs & 1) * 2;
            float mx = -1e30f;
#pragma unroll
            for (int nt = 0; nt < 8; ++nt)
                mx = fmaxf(mx, fmaxf(S[h][nt][off], S[h][nt][off + 1]));
            mx = fmaxf(mx, __shfl_xor_sync(0xffffffffu, mx, 1));
            mx = fmaxf(mx, __shfl_xor_sync(0xffffffffu, mx, 2));
            float mnew = fmaxf(m_s[rs], mx);
            float corr = __expf(m_s[rs] - mnew);
            m_s[rs] = mnew;
            float rsum = 0.0f;
#pragma unroll
            for (int nt = 0; nt < 8; ++nt) {
                float p0 = __expf(S[h][nt][off]     - mnew);
                float p1 = __expf(S[h][nt][off + 1] - mnew);
                S[h][nt][off]     = p0;
                S[h][nt][off + 1] = p1;
                rsum += p0 + p1;
            }
            rsum += __shfl_xor_sync(0xffffffffu, rsum, 1);
            rsum += __shfl_xor_sync(0xffffffffu, rsum, 2);
            l_s[rs] = l_s[rs] * corr + rsum;
#pragma unroll
            for (int nt = 0; nt < 8; ++nt) {
                Oa[h][nt][off]     *= corr;
                Oa[h][nt][off + 1] *= corr;
            }
        }

        // ---- Write P (own warp rows only -> warp sync suffices) ----
#pragma unroll
        for (int h = 0; h < 2; ++h) {
            int r0 = (w32 + h * 16 + grp) * 68;
#pragma unroll
            for (int nt = 0; nt < 8; ++nt) {
                int c = nt * 8 + 2 * lq;
                *(uint2*)&Ps[r0 + c] =
                    make_uint2(f2tf32(S[h][nt][0]), f2tf32(S[h][nt][1]));
                *(uint2*)&Ps[r0 + 8 * 68 + c] =
                    make_uint2(f2tf32(S[h][nt][2]), f2tf32(S[h][nt][3]));
            }
        }
        __syncwarp();

        // ---- O += P V : m32 x n64 x k64 per warp ----
#pragma unroll
        for (int kt = 0; kt < 8; ++kt) {
            const int kc = kt * 8;
            uint32_t a[2][4];
#pragma unroll
            for (int h = 0; h < 2; ++h) {
                int r = (w32 + h * 16 + grp) * 68 + kc + lq;
                a[h][0] = Ps[r];
                a[h][1] = Ps[r + 8 * 68];
                a[h][2] = Ps[r + 4];
                a[h][3] = Ps[r + 8 * 68 + 4];
            }
#pragma unroll
            for (int nt = 0; nt < 8; ++nt) {
                const int sw = (nt >= 4) ? 16 : 0;
                uint32_t b[2];
                int dn = (nt * 8 + grp) * 68;
                b[0] = Vt[dn + ((kc + lq) ^ sw)];
                b[1] = Vt[dn + ((kc + lq + 4) ^ sw)];
                mma_tf32(Oa[0][nt], a[0], b);
                mma_tf32(Oa[1][nt], a[1], b);
            }
        }
    }

    // ---- Finalize ----
    float inv[4];
#pragma unroll
    for (int r = 0; r < 4; ++r) inv[r] = 1.0f / l_s[r];
#pragma unroll
    for (int h = 0; h < 2; ++h) {
        size_t row = (size_t)(qrow0 + w32 + h * 16 + grp);
#pragma unroll
        for (int nt = 0; nt < 8; ++nt) {
            int col = col0 + nt * 8 + 2 * lq;
            *(float2*)&O[row * DM + col] =
                make_float2(Oa[h][nt][0] * inv[h * 2], Oa[h][nt][1] * inv[h * 2]);
            *(float2*)&O[(row + 8) * DM + col] =
                make_float2(Oa[h][nt][2] * inv[h * 2 + 1], Oa[h][nt][3] * inv[h * 2 + 1]);
        }
    }
}

// ---------------------------------------------------------------------------
extern "C" void kernel_launch(void* const* d_in, const int* in_sizes, int n_in,
                              void* d_out, int out_size) {
    const float* x  = (const float*)d_in[0];
    const float* wq = (const float*)d_in[1];
    const float* wk = (const float*)d_in[2];
    const float* wv = (const float*)d_in[3];
    const float* wo = (const float*)d_in[4];
    float* out = (float*)d_out;

    float *q, *k, *v, *ctx;
    cudaGetSymbolAddress((void**)&q,   g_q);
    cudaGetSymbolAddress((void**)&k,   g_k);
    cudaGetSymbolAddress((void**)&v,   g_v);
    cudaGetSymbolAddress((void**)&ctx, g_ctx);

    cudaFuncSetAttribute(attn_mma, cudaFuncAttributeMaxDynamicSharedMemorySize,
                         ATT_SMEM_BYTES);

    dim3 gemm_grid(DM / 128, SEQ / 128);
    gemm_tf32_nt<SEQ, DM, DM><<<gemm_grid, 256>>>(x, wq, q);
    gemm_tf32_nt<SEQ, DM, DM><<<gemm_grid, 256>>>(x, wk, k);
    gemm_tf32_nt<SEQ, DM, DM><<<gemm_grid, 256>>>(x, wv, v);

    attn_mma<<<dim3(SEQ / 128, NH), 128, ATT_SMEM_BYTES>>>(q, k, v, ctx);

    gemm_tf32_nt<SEQ, DM, DM><<<gemm_grid, 256>>>(ctx, wo, out);
}

// round 4
// speedup vs baseline: 2.4028x; 1.1169x over previous
#include <cuda_runtime.h>
#include <cstdint>

static constexpr int SEQ = 4096;
static constexpr int DM  = 1024;
static constexpr int NH  = 16;
static constexpr int HD  = 64;

// Scratch (allocation-free rule: device globals)
__device__ float g_q[SEQ * DM];
__device__ float g_k[SEQ * DM];
__device__ float g_v[SEQ * DM];
__device__ float g_ctx[SEQ * DM];

__device__ __forceinline__ uint32_t f2tf32(float f) {
    uint32_t u;
    asm("cvt.rna.tf32.f32 %0, %1;" : "=r"(u) : "f"(f));
    return u;
}

__device__ __forceinline__ void mma_tf32(float* d, const uint32_t* a, const uint32_t* b) {
    asm volatile(
        "mma.sync.aligned.m16n8k8.row.col.f32.tf32.tf32.f32 "
        "{%0,%1,%2,%3}, {%4,%5,%6,%7}, {%8,%9}, {%0,%1,%2,%3};"
        : "+f"(d[0]), "+f"(d[1]), "+f"(d[2]), "+f"(d[3])
        : "r"(a[0]), "r"(a[1]), "r"(a[2]), "r"(a[3]), "r"(b[0]), "r"(b[1]));
}

// ---------------------------------------------------------------------------
// TF32 tensor-core GEMM (NT): C[m,n] = sum_k A[m,k] * B[n,k]   (unchanged)
// ---------------------------------------------------------------------------
template <int M, int N, int K>
__global__ void __launch_bounds__(256) gemm_tf32_nt(const float* __restrict__ A,
                                                    const float* __restrict__ B,
                                                    float* __restrict__ C) {
    constexpr int BM = 128, BN = 128, BK = 16;
    constexpr int PAD = 20;
    __shared__ uint32_t As[BM][PAD];
    __shared__ uint32_t Bs[BN][PAD];

    const int tid  = threadIdx.x;
    const int warp = tid >> 5;
    const int lane = tid & 31;
    const int grp  = lane >> 2;
    const int lq   = lane & 3;

    const int warp_m = warp & 1;
    const int warp_n = warp >> 1;
    const int wm0 = warp_m * 64;
    const int wn0 = warp_n * 32;

    const int bm = blockIdx.y * BM;
    const int bn = blockIdx.x * BN;

    const int lrow = tid >> 1;
    const int lkh  = (tid & 1) * 8;
    const float* Ap = A + (size_t)(bm + lrow) * K + lkh;
    const float* Bp = B + (size_t)(bn + lrow) * K + lkh;

    float acc[4][4][4] = {};

    float4 ra0 = *(const float4*)(Ap);
    float4 ra1 = *(const float4*)(Ap + 4);
    float4 rb0 = *(const float4*)(Bp);
    float4 rb1 = *(const float4*)(Bp + 4);

    for (int k0 = 0; k0 < K; k0 += BK) {
        {
            uint4 ua0 = make_uint4(f2tf32(ra0.x), f2tf32(ra0.y), f2tf32(ra0.z), f2tf32(ra0.w));
            uint4 ua1 = make_uint4(f2tf32(ra1.x), f2tf32(ra1.y), f2tf32(ra1.z), f2tf32(ra1.w));
            uint4 ub0 = make_uint4(f2tf32(rb0.x), f2tf32(rb0.y), f2tf32(rb0.z), f2tf32(rb0.w));
            uint4 ub1 = make_uint4(f2tf32(rb1.x), f2tf32(rb1.y), f2tf32(rb1.z), f2tf32(rb1.w));
            *(uint4*)&As[lrow][lkh]     = ua0;
            *(uint4*)&As[lrow][lkh + 4] = ua1;
            *(uint4*)&Bs[lrow][lkh]     = ub0;
            *(uint4*)&Bs[lrow][lkh + 4] = ub1;
        }
        __syncthreads();

        if (k0 + BK < K) {
            ra0 = *(const float4*)(Ap + k0 + BK);
            ra1 = *(const float4*)(Ap + k0 + BK + 4);
            rb0 = *(const float4*)(Bp + k0 + BK);
            rb1 = *(const float4*)(Bp + k0 + BK + 4);
        }

#pragma unroll
        for (int ks = 0; ks < BK; ks += 8) {
            uint32_t afr[4][4];
            uint32_t bfr[4][2];
#pragma unroll
            for (int im = 0; im < 4; ++im) {
                int r0 = wm0 + im * 16;
                afr[im][0] = As[r0 + grp][ks + lq];
                afr[im][1] = As[r0 + grp + 8][ks + lq];
                afr[im][2] = As[r0 + grp][ks + lq + 4];
                afr[im][3] = As[r0 + grp + 8][ks + lq + 4];
            }
#pragma unroll
            for (int in = 0; in < 4; ++in) {
                int c0 = wn0 + in * 8;
                bfr[in][0] = Bs[c0 + grp][ks + lq];
                bfr[in][1] = Bs[c0 + grp][ks + lq + 4];
            }
#pragma unroll
            for (int im = 0; im < 4; ++im)
#pragma unroll
                for (int in = 0; in < 4; ++in)
                    mma_tf32(acc[im][in], afr[im], bfr[in]);
        }
        __syncthreads();
    }

#pragma unroll
    for (int im = 0; im < 4; ++im) {
#pragma unroll
        for (int in = 0; in < 4; ++in) {
            size_t row0 = (size_t)(bm + wm0 + im * 16 + grp);
            int col = bn + wn0 + in * 8 + 2 * lq;
            *(float2*)&C[row0 * N + col]       = make_float2(acc[im][in][0], acc[im][in][1]);
            *(float2*)&C[(row0 + 8) * N + col] = make_float2(acc[im][in][2], acc[im][in][3]);
        }
    }
}

// ---------------------------------------------------------------------------
// Flash attention, TF32 MMA. q-tile 128, kv-tile 64.
// 8 warps x m16 (256 threads), 2 CTAs/SM target.
// Smem (stride 68 words): Qs[128][68] Ks[64][68] Vt[64][68] Ps[128][68]
// Vt store swizzle: column jx = j ^ ((d>>4)<<3)  (conflict-free store+load)
// ---------------------------------------------------------------------------
static constexpr int ATT_SMEM_WORDS = (128 + 64 + 64 + 128) * 68;
static constexpr int ATT_SMEM_BYTES = ATT_SMEM_WORDS * 4;

__global__ void __launch_bounds__(256, 2) attn_mma(const float* __restrict__ Q,
                                                   const float* __restrict__ K,
                                                   const float* __restrict__ V,
                                                   float* __restrict__ O) {
    extern __shared__ uint32_t sm[];
    uint32_t* Qs = sm;                   // [128][68]
    uint32_t* Ks = Qs + 128 * 68;        // [64][68]
    uint32_t* Vt = Ks + 64 * 68;         // [64][68]
    uint32_t* Ps = Vt + 64 * 68;         // [128][68]

    const int tid  = threadIdx.x;
    const int warp = tid >> 5;
    const int lane = tid & 31;
    const int grp  = lane >> 2;
    const int lq   = lane & 3;
    const int head = blockIdx.y;
    const int qt   = (int)gridDim.x - 1 - (int)blockIdx.x;  // long CTAs first
    const int qrow0 = qt * 128;
    const int col0  = head * HD;
    const int w16   = warp * 16;

    // ---- Load Q tile (128x64), scale by 1/8, convert tf32 ----
    for (int idx = tid; idx < 128 * 16; idx += 256) {
        int row = idx >> 4;
        int p4  = (idx & 15) * 4;
        float4 qv = *(const float4*)&Q[(size_t)(qrow0 + row) * DM + col0 + p4];
        uint4 u = make_uint4(f2tf32(qv.x * 0.125f), f2tf32(qv.y * 0.125f),
                             f2tf32(qv.z * 0.125f), f2tf32(qv.w * 0.125f));
        *(uint4*)&Qs[row * 68 + p4] = u;
    }

    float Oa[8][4];
    float m_s[2], l_s[2];
#pragma unroll
    for (int nt = 0; nt < 8; ++nt)
#pragma unroll
        for (int c = 0; c < 4; ++c) Oa[nt][c] = 0.0f;
    m_s[0] = m_s[1] = -1e30f;
    l_s[0] = l_s[1] = 0.0f;

    // staging map: 4 threads per kv row (16 floats each)
    const int sj      = tid >> 2;          // kv row 0..63
    const int quarter = tid & 3;
    const int soff    = quarter * 16;      // d base
    const int vswz    = quarter << 3;      // Vt column XOR

    const int nkb = 2 * qt + 2;
    for (int kb = 0; kb < nkb; ++kb) {
        __syncthreads();  // prev iter finished reading Ks/Vt

        // ---- Stage K (natural [j][d]) and V^T (swizzled [d][j]) ----
        {
            const float* Kp = K + (size_t)(kb * 64 + sj) * DM + col0 + soff;
            const float* Vp = V + (size_t)(kb * 64 + sj) * DM + col0 + soff;
            const int jx = sj ^ vswz;
#pragma unroll
            for (int p = 0; p < 4; ++p) {
                float4 kv = *(const float4*)(Kp + p * 4);
                *(uint4*)&Ks[sj * 68 + soff + p * 4] =
                    make_uint4(f2tf32(kv.x), f2tf32(kv.y), f2tf32(kv.z), f2tf32(kv.w));
                float4 vv = *(const float4*)(Vp + p * 4);
                int d = soff + p * 4;
                Vt[(d + 0) * 68 + jx] = f2tf32(vv.x);
                Vt[(d + 1) * 68 + jx] = f2tf32(vv.y);
                Vt[(d + 2) * 68 + jx] = f2tf32(vv.z);
                Vt[(d + 3) * 68 + jx] = f2tf32(vv.w);
            }
        }
        __syncthreads();

        // ---- S = Q K^T : m16 x n64 x k64 per warp ----
        float S[8][4];
#pragma unroll
        for (int nt = 0; nt < 8; ++nt)
#pragma unroll
            for (int c = 0; c < 4; ++c) S[nt][c] = 0.0f;

#pragma unroll
        for (int kt = 0; kt < 8; ++kt) {
            const int kc = kt * 8;
            uint32_t a[4];
            {
                int r = (w16 + grp) * 68 + kc + lq;
                a[0] = Qs[r];
                a[1] = Qs[r + 8 * 68];
                a[2] = Qs[r + 4];
                a[3] = Qs[r + 8 * 68 + 4];
            }
#pragma unroll
            for (int nt = 0; nt < 8; ++nt) {
                uint32_t b[2];
                int o = (nt * 8 + grp) * 68 + kc + lq;
                b[0] = Ks[o];
                b[1] = Ks[o + 4];
                mma_tf32(S[nt], a, b);
            }
        }

        // ---- Causal mask (only last two kv blocks of the tile) ----
        if (kb >= 2 * qt) {
#pragma unroll
            for (int nt = 0; nt < 8; ++nt)
#pragma unroll
                for (int c = 0; c < 4; ++c) {
                    int qi = qrow0 + w16 + grp + ((c >> 1) << 3);
                    int kj = kb * 64 + nt * 8 + 2 * lq + (c & 1);
                    if (kj > qi) S[nt][c] = -10000.0f;
                }
        }

        // ---- Online softmax: 2 row-slots (rows grp, grp+8) ----
#pragma unroll
        for (int rs = 0; rs < 2; ++rs) {
            const int off = rs * 2;
            float mx = -1e30f;
#pragma unroll
            for (int nt = 0; nt < 8; ++nt)
                mx = fmaxf(mx, fmaxf(S[nt][off], S[nt][off + 1]));
            mx = fmaxf(mx, __shfl_xor_sync(0xffffffffu, mx, 1));
            mx = fmaxf(mx, __shfl_xor_sync(0xffffffffu, mx, 2));
            float mnew = fmaxf(m_s[rs], mx);
            float corr = __expf(m_s[rs] - mnew);
            m_s[rs] = mnew;
            float rsum = 0.0f;
#pragma unroll
            for (int nt = 0; nt < 8; ++nt) {
                float p0 = __expf(S[nt][off]     - mnew);
                float p1 = __expf(S[nt][off + 1] - mnew);
                S[nt][off]     = p0;
                S[nt][off + 1] = p1;
                rsum += p0 + p1;
            }
            rsum += __shfl_xor_sync(0xffffffffu, rsum, 1);
            rsum += __shfl_xor_sync(0xffffffffu, rsum, 2);
            l_s[rs] = l_s[rs] * corr + rsum;
#pragma unroll
            for (int nt = 0; nt < 8; ++nt) {
                Oa[nt][off]     *= corr;
                Oa[nt][off + 1] *= corr;
            }
        }

        // ---- Write P (own warp rows only -> warp sync suffices) ----
        {
            int r0 = (w16 + grp) * 68;
#pragma unroll
            for (int nt = 0; nt < 8; ++nt) {
                int c = nt * 8 + 2 * lq;
                *(uint2*)&Ps[r0 + c] =
                    make_uint2(f2tf32(S[nt][0]), f2tf32(S[nt][1]));
                *(uint2*)&Ps[r0 + 8 * 68 + c] =
                    make_uint2(f2tf32(S[nt][2]), f2tf32(S[nt][3]));
            }
        }
        __syncwarp();

        // ---- O += P V : m16 x n64 x k64 per warp ----
#pragma unroll
        for (int kt = 0; kt < 8; ++kt) {
            const int kc = kt * 8;
            uint32_t a[4];
            {
                int r = (w16 + grp) * 68 + kc + lq;
                a[0] = Ps[r];
                a[1] = Ps[r + 8 * 68];
                a[2] = Ps[r + 4];
                a[3] = Ps[r + 8 * 68 + 4];
            }
#pragma unroll
            for (int nt = 0; nt < 8; ++nt) {
                const int sw = (nt >> 1) << 3;   // (d>>4)<<3 with d = nt*8+grp
                uint32_t b[2];
                int dn = (nt * 8 + grp) * 68;
                b[0] = Vt[dn + ((kc + lq) ^ sw)];
                b[1] = Vt[dn + ((kc + lq + 4) ^ sw)];
                mma_tf32(Oa[nt], a, b);
            }
        }
    }

    // ---- Finalize ----
    const float inv0 = 1.0f / l_s[0];
    const float inv1 = 1.0f / l_s[1];
    {
        size_t row = (size_t)(qrow0 + w16 + grp);
#pragma unroll
        for (int nt = 0; nt < 8; ++nt) {
            int col = col0 + nt * 8 + 2 * lq;
            *(float2*)&O[row * DM + col] =
                make_float2(Oa[nt][0] * inv0, Oa[nt][1] * inv0);
            *(float2*)&O[(row + 8) * DM + col] =
                make_float2(Oa[nt][2] * inv1, Oa[nt][3] * inv1);
        }
    }
}

// ---------------------------------------------------------------------------
extern "C" void kernel_launch(void* const* d_in, const int* in_sizes, int n_in,
                              void* d_out, int out_size) {
    const float* x  = (const float*)d_in[0];
    const float* wq = (const float*)d_in[1];
    const float* wk = (const float*)d_in[2];
    const float* wv = (const float*)d_in[3];
    const float* wo = (const float*)d_in[4];
    float* out = (float*)d_out;

    float *q, *k, *v, *ctx;
    cudaGetSymbolAddress((void**)&q,   g_q);
    cudaGetSymbolAddress((void**)&k,   g_k);
    cudaGetSymbolAddress((void**)&v,   g_v);
    cudaGetSymbolAddress((void**)&ctx, g_ctx);

    cudaFuncSetAttribute(attn_mma, cudaFuncAttributeMaxDynamicSharedMemorySize,
                         ATT_SMEM_BYTES);

    dim3 gemm_grid(DM / 128, SEQ / 128);
    gemm_tf32_nt<SEQ, DM, DM><<<gemm_grid, 256>>>(x, wq, q);
    gemm_tf32_nt<SEQ, DM, DM><<<gemm_grid, 256>>>(x, wk, k);
    gemm_tf32_nt<SEQ, DM, DM><<<gemm_grid, 256>>>(x, wv, v);

    attn_mma<<<dim3(SEQ / 128, NH), 256, ATT_SMEM_BYTES>>>(q, k, v, ctx);

    gemm_tf32_nt<SEQ, DM, DM><<<gemm_grid, 256>>>(ctx, wo, out);
}

// round 5
// speedup vs baseline: 2.4580x; 1.0230x over previous
#include <cuda_runtime.h>
#include <cstdint>

static constexpr int SEQ = 4096;
static constexpr int DM  = 1024;
static constexpr int NH  = 16;
static constexpr int HD  = 64;

// Scratch (allocation-free rule: device globals)
__device__ float g_q[SEQ * DM];
__device__ float g_k[SEQ * DM];
__device__ float g_v[SEQ * DM];
__device__ float g_ctx[SEQ * DM];

__device__ __forceinline__ uint32_t f2tf32(float f) {
    uint32_t u;
    asm("cvt.rna.tf32.f32 %0, %1;" : "=r"(u) : "f"(f));
    return u;
}

__device__ __forceinline__ void mma_tf32(float* d, const uint32_t* a, const uint32_t* b) {
    asm volatile(
        "mma.sync.aligned.m16n8k8.row.col.f32.tf32.tf32.f32 "
        "{%0,%1,%2,%3}, {%4,%5,%6,%7}, {%8,%9}, {%0,%1,%2,%3};"
        : "+f"(d[0]), "+f"(d[1]), "+f"(d[2]), "+f"(d[3])
        : "r"(a[0]), "r"(a[1]), "r"(a[2]), "r"(a[3]), "r"(b[0]), "r"(b[1]));
}

__device__ __forceinline__ uint32_t smem_u32(const void* p) {
    uint32_t a;
    asm("{ .reg .u64 t; cvta.to.shared.u64 t, %1; cvt.u32.u64 %0, t; }"
        : "=r"(a) : "l"(p));
    return a;
}

__device__ __forceinline__ void cp16(uint32_t dst, const void* src) {
    asm volatile("cp.async.cg.shared.global [%0], [%1], 16;" :: "r"(dst), "l"(src));
}
#define CP_COMMIT() asm volatile("cp.async.commit_group;" ::: "memory")
#define CP_WAIT0()  asm volatile("cp.async.wait_group 0;" ::: "memory")

// ---------------------------------------------------------------------------
// TF32 tensor-core GEMM (NT): C[m,n] = sum_k A[m,k] * B[n,k]
// CVT_OUT: store tf32-rounded bits (rna, scale folded) for attention cp.async.
// ---------------------------------------------------------------------------
template <int M, int N, int K, bool CVT_OUT>
__global__ void __launch_bounds__(256) gemm_tf32_nt(const float* __restrict__ A,
                                                    const float* __restrict__ B,
                                                    float* __restrict__ C,
                                                    float out_scale) {
    constexpr int BM = 128, BN = 128, BK = 16;
    constexpr int PAD = 20;
    __shared__ uint32_t As[BM][PAD];
    __shared__ uint32_t Bs[BN][PAD];

    const int tid  = threadIdx.x;
    const int warp = tid >> 5;
    const int lane = tid & 31;
    const int grp  = lane >> 2;
    const int lq   = lane & 3;

    const int warp_m = warp & 1;
    const int warp_n = warp >> 1;
    const int wm0 = warp_m * 64;
    const int wn0 = warp_n * 32;

    const int bm = blockIdx.y * BM;
    const int bn = blockIdx.x * BN;

    const int lrow = tid >> 1;
    const int lkh  = (tid & 1) * 8;
    const float* Ap = A + (size_t)(bm + lrow) * K + lkh;
    const float* Bp = B + (size_t)(bn + lrow) * K + lkh;

    float acc[4][4][4] = {};

    float4 ra0 = *(const float4*)(Ap);
    float4 ra1 = *(const float4*)(Ap + 4);
    float4 rb0 = *(const float4*)(Bp);
    float4 rb1 = *(const float4*)(Bp + 4);

    for (int k0 = 0; k0 < K; k0 += BK) {
        {
            uint4 ua0 = make_uint4(f2tf32(ra0.x), f2tf32(ra0.y), f2tf32(ra0.z), f2tf32(ra0.w));
            uint4 ua1 = make_uint4(f2tf32(ra1.x), f2tf32(ra1.y), f2tf32(ra1.z), f2tf32(ra1.w));
            uint4 ub0 = make_uint4(f2tf32(rb0.x), f2tf32(rb0.y), f2tf32(rb0.z), f2tf32(rb0.w));
            uint4 ub1 = make_uint4(f2tf32(rb1.x), f2tf32(rb1.y), f2tf32(rb1.z), f2tf32(rb1.w));
            *(uint4*)&As[lrow][lkh]     = ua0;
            *(uint4*)&As[lrow][lkh + 4] = ua1;
            *(uint4*)&Bs[lrow][lkh]     = ub0;
            *(uint4*)&Bs[lrow][lkh + 4] = ub1;
        }
        __syncthreads();

        if (k0 + BK < K) {
            ra0 = *(const float4*)(Ap + k0 + BK);
            ra1 = *(const float4*)(Ap + k0 + BK + 4);
            rb0 = *(const float4*)(Bp + k0 + BK);
            rb1 = *(const float4*)(Bp + k0 + BK + 4);
        }

#pragma unroll
        for (int ks = 0; ks < BK; ks += 8) {
            uint32_t afr[4][4];
            uint32_t bfr[4][2];
#pragma unroll
            for (int im = 0; im < 4; ++im) {
                int r0 = wm0 + im * 16;
                afr[im][0] = As[r0 + grp][ks + lq];
                afr[im][1] = As[r0 + grp + 8][ks + lq];
                afr[im][2] = As[r0 + grp][ks + lq + 4];
                afr[im][3] = As[r0 + grp + 8][ks + lq + 4];
            }
#pragma unroll
            for (int in = 0; in < 4; ++in) {
                int c0 = wn0 + in * 8;
                bfr[in][0] = Bs[c0 + grp][ks + lq];
                bfr[in][1] = Bs[c0 + grp][ks + lq + 4];
            }
#pragma unroll
            for (int im = 0; im < 4; ++im)
#pragma unroll
                for (int in = 0; in < 4; ++in)
                    mma_tf32(acc[im][in], afr[im], bfr[in]);
        }
        __syncthreads();
    }

#pragma unroll
    for (int im = 0; im < 4; ++im) {
#pragma unroll
        for (int in = 0; in < 4; ++in) {
            size_t row0 = (size_t)(bm + wm0 + im * 16 + grp);
            int col = bn + wn0 + in * 8 + 2 * lq;
            float o0 = acc[im][in][0], o1 = acc[im][in][1];
            float o2 = acc[im][in][2], o3 = acc[im][in][3];
            if (CVT_OUT) {
                o0 = __uint_as_float(f2tf32(o0 * out_scale));
                o1 = __uint_as_float(f2tf32(o1 * out_scale));
                o2 = __uint_as_float(f2tf32(o2 * out_scale));
                o3 = __uint_as_float(f2tf32(o3 * out_scale));
            }
            *(float2*)&C[row0 * N + col]       = make_float2(o0, o1);
            *(float2*)&C[(row0 + 8) * N + col] = make_float2(o2, o3);
        }
    }
}

// ---------------------------------------------------------------------------
// Flash attention, TF32 MMA, no-max softmax, cp.async double-buffered K/V,
// P kept in registers (shuffle permute to A-fragment layout).
// q-tile 128, kv-tile 64, 8 warps x m16, 2 CTAs/SM.
// Smem: Qs[128][68] | Ks[2][64][68] | Vs[2][64][72]  (104 KB)
// Inputs already tf32-rounded bits (GEMM epilogue), Q pre-scaled by 1/8.
// ---------------------------------------------------------------------------
static constexpr int QS_ST = 68;
static constexpr int KS_ST = 68;
static constexpr int VS_ST = 72;
static constexpr int ATT_SMEM_WORDS = 128 * QS_ST + 2 * 64 * KS_ST + 2 * 64 * VS_ST;
static constexpr int ATT_SMEM_BYTES = ATT_SMEM_WORDS * 4;

__global__ void __launch_bounds__(256, 2) attn_mma(const float* __restrict__ Q,
                                                   const float* __restrict__ K,
                                                   const float* __restrict__ V,
                                                   float* __restrict__ O) {
    extern __shared__ uint32_t sm[];
    uint32_t* Qs = sm;                         // [128][68]
    uint32_t* Ks = Qs + 128 * QS_ST;           // [2][64][68]
    uint32_t* Vs = Ks + 2 * 64 * KS_ST;        // [2][64][72]

    const int tid  = threadIdx.x;
    const int lane = tid & 31;
    const int grp  = lane >> 2;
    const int lq   = lane & 3;
    const int head = blockIdx.y;
    const int qt   = (int)gridDim.x - 1 - (int)blockIdx.x;  // long CTAs first
    const int qrow0 = qt * 128;
    const int col0  = head * HD;
    const int w16   = (tid >> 5) * 16;

    // staging maps
    const int krow = tid >> 2;             // kv row 0..63
    const int kf0  = (tid & 3) * 16;       // float offset (4 chunks of 16B)
    const float* Ksrc = K + (size_t)krow * DM + col0 + kf0;
    const float* Vsrc = V + (size_t)krow * DM + col0 + kf0;
    const uint32_t ksd = smem_u32(Ks) + (uint32_t)(krow * KS_ST + kf0) * 4;
    const uint32_t vsd = smem_u32(Vs) + (uint32_t)(krow * VS_ST + kf0) * 4;

    // ---- Prologue: Q tile + K(0),V(0) as cp.async group 0 ----
    {
        int qrow = tid >> 1;
        int qf0  = (tid & 1) * 32;
        const float* qsrc = Q + (size_t)(qrow0 + qrow) * DM + col0 + qf0;
        uint32_t qdst = smem_u32(Qs) + (uint32_t)(qrow * QS_ST + qf0) * 4;
#pragma unroll
        for (int p = 0; p < 8; ++p) cp16(qdst + p * 16, qsrc + p * 4);
#pragma unroll
        for (int p = 0; p < 4; ++p) {
            cp16(ksd + p * 16, Ksrc + p * 4);
            cp16(vsd + p * 16, Vsrc + p * 4);
        }
        CP_COMMIT();
    }

    float Oa[8][4];
    float l_s[2] = {0.0f, 0.0f};
#pragma unroll
    for (int nt = 0; nt < 8; ++nt)
#pragma unroll
        for (int c = 0; c < 4; ++c) Oa[nt][c] = 0.0f;

    const int nkb = 2 * qt + 2;
    for (int kb = 0; kb < nkb; ++kb) {
        CP_WAIT0();        // group(kb) complete (issued during iter kb-1)
        __syncthreads();   // visible block-wide; buffers (kb+1)&1 free

        // ---- Issue K/V for kb+1 (fully overlapped with this iter) ----
        if (kb + 1 < nkb) {
            const int b = (kb + 1) & 1;
            const float* Kp = Ksrc + (size_t)(kb + 1) * 64 * DM;
            const float* Vp = Vsrc + (size_t)(kb + 1) * 64 * DM;
            const uint32_t kd = ksd + (uint32_t)(b * 64 * KS_ST) * 4;
            const uint32_t vd = vsd + (uint32_t)(b * 64 * VS_ST) * 4;
#pragma unroll
            for (int p = 0; p < 4; ++p) {
                cp16(kd + p * 16, Kp + p * 4);
                cp16(vd + p * 16, Vp + p * 4);
            }
            CP_COMMIT();
        }

        const uint32_t* KsC = Ks + (kb & 1) * 64 * KS_ST;
        const uint32_t* VsC = Vs + (kb & 1) * 64 * VS_ST;

        // ---- S = Q K^T : m16 x n64 x k64 per warp ----
        float S[8][4];
#pragma unroll
        for (int nt = 0; nt < 8; ++nt)
#pragma unroll
            for (int c = 0; c < 4; ++c) S[nt][c] = 0.0f;

#pragma unroll
        for (int kt = 0; kt < 8; ++kt) {
            const int kc = kt * 8;
            uint32_t a[4];
            {
                int r = (w16 + grp) * QS_ST + kc + lq;
                a[0] = Qs[r];
                a[1] = Qs[r + 8 * QS_ST];
                a[2] = Qs[r + 4];
                a[3] = Qs[r + 8 * QS_ST + 4];
            }
#pragma unroll
            for (int nt = 0; nt < 8; ++nt) {
                uint32_t b[2];
                int o = (nt * 8 + grp) * KS_ST + kc + lq;
                b[0] = KsC[o];
                b[1] = KsC[o + 4];
                mma_tf32(S[nt], a, b);
            }
        }

        // ---- Causal mask (last two kv blocks of the tile only) ----
        if (kb >= 2 * qt) {
#pragma unroll
            for (int nt = 0; nt < 8; ++nt)
#pragma unroll
                for (int c = 0; c < 4; ++c) {
                    int qi = qrow0 + w16 + grp + ((c >> 1) << 3);
                    int kj = kb * 64 + nt * 8 + 2 * lq + (c & 1);
                    if (kj > qi) S[nt][c] = -10000.0f;
                }
        }

        // ---- No-max softmax: p = exp(s); accumulate partial l; cvt tf32 ----
#pragma unroll
        for (int nt = 0; nt < 8; ++nt) {
            float p0 = __expf(S[nt][0]);
            float p1 = __expf(S[nt][1]);
            float p2 = __expf(S[nt][2]);
            float p3 = __expf(S[nt][3]);
            l_s[0] += p0 + p1;
            l_s[1] += p2 + p3;
            S[nt][0] = __uint_as_float(f2tf32(p0));
            S[nt][1] = __uint_as_float(f2tf32(p1));
            S[nt][2] = __uint_as_float(f2tf32(p2));
            S[nt][3] = __uint_as_float(f2tf32(p3));
        }

        // ---- O += P V : P A-fragments built via warp shuffles ----
        const int src_a = (lane & 28) | (lq >> 1);
        const int src_b = src_a | 2;
        const bool hi = lq & 1;
#pragma unroll
        for (int kt = 0; kt < 8; ++kt) {
            uint32_t a[4];
            {
                float v0 = __shfl_sync(0xffffffffu, S[kt][0], src_a);
                float v1 = __shfl_sync(0xffffffffu, S[kt][1], src_a);
                float v2 = __shfl_sync(0xffffffffu, S[kt][2], src_a);
                float v3 = __shfl_sync(0xffffffffu, S[kt][3], src_a);
                float w0 = __shfl_sync(0xffffffffu, S[kt][0], src_b);
                float w1 = __shfl_sync(0xffffffffu, S[kt][1], src_b);
                float w2 = __shfl_sync(0xffffffffu, S[kt][2], src_b);
                float w3 = __shfl_sync(0xffffffffu, S[kt][3], src_b);
                a[0] = __float_as_uint(hi ? v1 : v0);
                a[1] = __float_as_uint(hi ? v3 : v2);
                a[2] = __float_as_uint(hi ? w1 : w0);
                a[3] = __float_as_uint(hi ? w3 : w2);
            }
            const int kc = kt * 8;
#pragma unroll
            for (int nt = 0; nt < 8; ++nt) {
                uint32_t b[2];
                b[0] = VsC[(kc + lq) * VS_ST + nt * 8 + grp];
                b[1] = VsC[(kc + lq + 4) * VS_ST + nt * 8 + grp];
                mma_tf32(Oa[nt], a, b);
            }
        }
    }

    // ---- Final l reduction + writeback ----
    l_s[0] += __shfl_xor_sync(0xffffffffu, l_s[0], 1);
    l_s[0] += __shfl_xor_sync(0xffffffffu, l_s[0], 2);
    l_s[1] += __shfl_xor_sync(0xffffffffu, l_s[1], 1);
    l_s[1] += __shfl_xor_sync(0xffffffffu, l_s[1], 2);
    const float inv0 = 1.0f / l_s[0];
    const float inv1 = 1.0f / l_s[1];
    {
        size_t row = (size_t)(qrow0 + w16 + grp);
#pragma unroll
        for (int nt = 0; nt < 8; ++nt) {
            int col = col0 + nt * 8 + 2 * lq;
            *(float2*)&O[row * DM + col] =
                make_float2(Oa[nt][0] * inv0, Oa[nt][1] * inv0);
            *(float2*)&O[(row + 8) * DM + col] =
                make_float2(Oa[nt][2] * inv1, Oa[nt][3] * inv1);
        }
    }
}

// ---------------------------------------------------------------------------
extern "C" void kernel_launch(void* const* d_in, const int* in_sizes, int n_in,
                              void* d_out, int out_size) {
    const float* x  = (const float*)d_in[0];
    const float* wq = (const float*)d_in[1];
    const float* wk = (const float*)d_in[2];
    const float* wv = (const float*)d_in[3];
    const float* wo = (const float*)d_in[4];
    float* out = (float*)d_out;

    float *q, *k, *v, *ctx;
    cudaGetSymbolAddress((void**)&q,   g_q);
    cudaGetSymbolAddress((void**)&k,   g_k);
    cudaGetSymbolAddress((void**)&v,   g_v);
    cudaGetSymbolAddress((void**)&ctx, g_ctx);

    cudaFuncSetAttribute(attn_mma, cudaFuncAttributeMaxDynamicSharedMemorySize,
                         ATT_SMEM_BYTES);

    dim3 gemm_grid(DM / 128, SEQ / 128);
    gemm_tf32_nt<SEQ, DM, DM, true><<<gemm_grid, 256>>>(x, wq, q, 0.125f);
    gemm_tf32_nt<SEQ, DM, DM, true><<<gemm_grid, 256>>>(x, wk, k, 1.0f);
    gemm_tf32_nt<SEQ, DM, DM, true><<<gemm_grid, 256>>>(x, wv, v, 1.0f);

    attn_mma<<<dim3(SEQ / 128, NH), 256, ATT_SMEM_BYTES>>>(q, k, v, ctx);

    gemm_tf32_nt<SEQ, DM, DM, false><<<gemm_grid, 256>>>(ctx, wo, out, 1.0f);
}

// round 6
// speedup vs baseline: 2.6063x; 1.0604x over previous
#include <cuda_runtime.h>
#include <cstdint>

static constexpr int SEQ = 4096;
static constexpr int DM  = 1024;
static constexpr int NH  = 16;
static constexpr int HD  = 64;

// Scratch (allocation-free rule: device globals)
__device__ float g_q[SEQ * DM];
__device__ float g_k[SEQ * DM];
__device__ float g_v[SEQ * DM];
__device__ float g_ctx[SEQ * DM];

__device__ __forceinline__ uint32_t f2tf32(float f) {
    uint32_t u;
    asm("cvt.rna.tf32.f32 %0, %1;" : "=r"(u) : "f"(f));
    return u;
}

__device__ __forceinline__ void mma_tf32(float* d, const uint32_t* a, const uint32_t* b) {
    asm volatile(
        "mma.sync.aligned.m16n8k8.row.col.f32.tf32.tf32.f32 "
        "{%0,%1,%2,%3}, {%4,%5,%6,%7}, {%8,%9}, {%0,%1,%2,%3};"
        : "+f"(d[0]), "+f"(d[1]), "+f"(d[2]), "+f"(d[3])
        : "r"(a[0]), "r"(a[1]), "r"(a[2]), "r"(a[3]), "r"(b[0]), "r"(b[1]));
}

__device__ __forceinline__ uint32_t smem_u32(const void* p) {
    uint32_t a;
    asm("{ .reg .u64 t; cvta.to.shared.u64 t, %1; cvt.u32.u64 %0, t; }"
        : "=r"(a) : "l"(p));
    return a;
}

__device__ __forceinline__ void cp16(uint32_t dst, const void* src) {
    asm volatile("cp.async.cg.shared.global [%0], [%1], 16;" :: "r"(dst), "l"(src));
}
#define CP_COMMIT() asm volatile("cp.async.commit_group;" ::: "memory")
#define CP_WAIT0()  asm volatile("cp.async.wait_group 0;" ::: "memory")

// ---------------------------------------------------------------------------
// TF32 GEMM (NT), 2-stage smem double buffer, ONE sync per BK=16 iteration.
// gridDim.z selects (B, C, scale) -> fused QKV in one launch (z=3) or WO (z=1).
// CVT_OUT: store tf32-rounded bits (rna, scale folded) for attention cp.async.
// ---------------------------------------------------------------------------
template <int M, int N, int K, bool CVT_OUT>
__global__ void __launch_bounds__(256, 2)
gemm_tf32_db(const float* __restrict__ A,
             const float* __restrict__ B0, const float* __restrict__ B1,
             const float* __restrict__ B2,
             float* __restrict__ C0, float* __restrict__ C1, float* __restrict__ C2,
             float scale0) {
    constexpr int BM = 128, BN = 128, BK = 16;
    constexpr int PAD = 20;
    __shared__ uint32_t As[2][BM][PAD];
    __shared__ uint32_t Bs[2][BN][PAD];

    const float* B = (blockIdx.z == 0) ? B0 : (blockIdx.z == 1 ? B1 : B2);
    float*       C = (blockIdx.z == 0) ? C0 : (blockIdx.z == 1 ? C1 : C2);
    const float out_scale = (blockIdx.z == 0) ? scale0 : 1.0f;

    const int tid  = threadIdx.x;
    const int warp = tid >> 5;
    const int lane = tid & 31;
    const int grp  = lane >> 2;
    const int lq   = lane & 3;

    const int wm0 = (warp & 1) * 64;
    const int wn0 = (warp >> 1) * 32;

    const int bm = blockIdx.y * BM;
    const int bn = blockIdx.x * BN;

    const int lrow = tid >> 1;
    const int lkh  = (tid & 1) * 8;
    const float* Ap = A + (size_t)(bm + lrow) * K + lkh;
    const float* Bp = B + (size_t)(bn + lrow) * K + lkh;

    float acc[4][4][4] = {};

    // preload tile 0 into registers
    float4 ra0 = *(const float4*)(Ap);
    float4 ra1 = *(const float4*)(Ap + 4);
    float4 rb0 = *(const float4*)(Bp);
    float4 rb1 = *(const float4*)(Bp + 4);

    for (int k0 = 0; k0 < K; k0 += BK) {
        const int s = (k0 >> 4) & 1;
        // stage regs -> smem (tf32 rna)
        *(uint4*)&As[s][lrow][lkh] =
            make_uint4(f2tf32(ra0.x), f2tf32(ra0.y), f2tf32(ra0.z), f2tf32(ra0.w));
        *(uint4*)&As[s][lrow][lkh + 4] =
            make_uint4(f2tf32(ra1.x), f2tf32(ra1.y), f2tf32(ra1.z), f2tf32(ra1.w));
        *(uint4*)&Bs[s][lrow][lkh] =
            make_uint4(f2tf32(rb0.x), f2tf32(rb0.y), f2tf32(rb0.z), f2tf32(rb0.w));
        *(uint4*)&Bs[s][lrow][lkh + 4] =
            make_uint4(f2tf32(rb1.x), f2tf32(rb1.y), f2tf32(rb1.z), f2tf32(rb1.w));
        __syncthreads();  // the only barrier per iteration

        // prefetch next tile (completes under the MMAs)
        if (k0 + BK < K) {
            ra0 = *(const float4*)(Ap + k0 + BK);
            ra1 = *(const float4*)(Ap + k0 + BK + 4);
            rb0 = *(const float4*)(Bp + k0 + BK);
            rb1 = *(const float4*)(Bp + k0 + BK + 4);
        }

#pragma unroll
        for (int ks = 0; ks < BK; ks += 8) {
            uint32_t afr[4][4];
            uint32_t bfr[4][2];
#pragma unroll
            for (int im = 0; im < 4; ++im) {
                int r0 = wm0 + im * 16;
                afr[im][0] = As[s][r0 + grp][ks + lq];
                afr[im][1] = As[s][r0 + grp + 8][ks + lq];
                afr[im][2] = As[s][r0 + grp][ks + lq + 4];
                afr[im][3] = As[s][r0 + grp + 8][ks + lq + 4];
            }
#pragma unroll
            for (int in = 0; in < 4; ++in) {
                int c0 = wn0 + in * 8;
                bfr[in][0] = Bs[s][c0 + grp][ks + lq];
                bfr[in][1] = Bs[s][c0 + grp][ks + lq + 4];
            }
#pragma unroll
            for (int im = 0; im < 4; ++im)
#pragma unroll
                for (int in = 0; in < 4; ++in)
                    mma_tf32(acc[im][in], afr[im], bfr[in]);
        }
        // no trailing sync: next STS targets the other stage; stage reuse is
        // separated by the next iteration's barrier.
    }

#pragma unroll
    for (int im = 0; im < 4; ++im) {
#pragma unroll
        for (int in = 0; in < 4; ++in) {
            size_t row0 = (size_t)(bm + wm0 + im * 16 + grp);
            int col = bn + wn0 + in * 8 + 2 * lq;
            float o0 = acc[im][in][0], o1 = acc[im][in][1];
            float o2 = acc[im][in][2], o3 = acc[im][in][3];
            if (CVT_OUT) {
                o0 = __uint_as_float(f2tf32(o0 * out_scale));
                o1 = __uint_as_float(f2tf32(o1 * out_scale));
                o2 = __uint_as_float(f2tf32(o2 * out_scale));
                o3 = __uint_as_float(f2tf32(o3 * out_scale));
            }
            *(float2*)&C[row0 * N + col]       = make_float2(o0, o1);
            *(float2*)&C[(row0 + 8) * N + col] = make_float2(o2, o3);
        }
    }
}

// ---------------------------------------------------------------------------
// Flash attention, TF32 MMA, no-max softmax, cp.async double-buffered K/V,
// P kept in registers (shuffle permute to A-fragment layout).
// (unchanged from round 5 passing version)
// ---------------------------------------------------------------------------
static constexpr int QS_ST = 68;
static constexpr int KS_ST = 68;
static constexpr int VS_ST = 72;
static constexpr int ATT_SMEM_WORDS = 128 * QS_ST + 2 * 64 * KS_ST + 2 * 64 * VS_ST;
static constexpr int ATT_SMEM_BYTES = ATT_SMEM_WORDS * 4;

__global__ void __launch_bounds__(256, 2) attn_mma(const float* __restrict__ Q,
                                                   const float* __restrict__ K,
                                                   const float* __restrict__ V,
                                                   float* __restrict__ O) {
    extern __shared__ uint32_t sm[];
    uint32_t* Qs = sm;                         // [128][68]
    uint32_t* Ks = Qs + 128 * QS_ST;           // [2][64][68]
    uint32_t* Vs = Ks + 2 * 64 * KS_ST;        // [2][64][72]

    const int tid  = threadIdx.x;
    const int lane = tid & 31;
    const int grp  = lane >> 2;
    const int lq   = lane & 3;
    const int head = blockIdx.y;
    const int qt   = (int)gridDim.x - 1 - (int)blockIdx.x;  // long CTAs first
    const int qrow0 = qt * 128;
    const int col0  = head * HD;
    const int w16   = (tid >> 5) * 16;

    const int krow = tid >> 2;
    const int kf0  = (tid & 3) * 16;
    const float* Ksrc = K + (size_t)krow * DM + col0 + kf0;
    const float* Vsrc = V + (size_t)krow * DM + col0 + kf0;
    const uint32_t ksd = smem_u32(Ks) + (uint32_t)(krow * KS_ST + kf0) * 4;
    const uint32_t vsd = smem_u32(Vs) + (uint32_t)(krow * VS_ST + kf0) * 4;

    {
        int qrow = tid >> 1;
        int qf0  = (tid & 1) * 32;
        const float* qsrc = Q + (size_t)(qrow0 + qrow) * DM + col0 + qf0;
        uint32_t qdst = smem_u32(Qs) + (uint32_t)(qrow * QS_ST + qf0) * 4;
#pragma unroll
        for (int p = 0; p < 8; ++p) cp16(qdst + p * 16, qsrc + p * 4);
#pragma unroll
        for (int p = 0; p < 4; ++p) {
            cp16(ksd + p * 16, Ksrc + p * 4);
            cp16(vsd + p * 16, Vsrc + p * 4);
        }
        CP_COMMIT();
    }

    float Oa[8][4];
    float l_s[2] = {0.0f, 0.0f};
#pragma unroll
    for (int nt = 0; nt < 8; ++nt)
#pragma unroll
        for (int c = 0; c < 4; ++c) Oa[nt][c] = 0.0f;

    const int nkb = 2 * qt + 2;
    for (int kb = 0; kb < nkb; ++kb) {
        CP_WAIT0();
        __syncthreads();

        if (kb + 1 < nkb) {
            const int b = (kb + 1) & 1;
            const float* Kp = Ksrc + (size_t)(kb + 1) * 64 * DM;
            const float* Vp = Vsrc + (size_t)(kb + 1) * 64 * DM;
            const uint32_t kd = ksd + (uint32_t)(b * 64 * KS_ST) * 4;
            const uint32_t vd = vsd + (uint32_t)(b * 64 * VS_ST) * 4;
#pragma unroll
            for (int p = 0; p < 4; ++p) {
                cp16(kd + p * 16, Kp + p * 4);
                cp16(vd + p * 16, Vp + p * 4);
            }
            CP_COMMIT();
        }

        const uint32_t* KsC = Ks + (kb & 1) * 64 * KS_ST;
        const uint32_t* VsC = Vs + (kb & 1) * 64 * VS_ST;

        float S[8][4];
#pragma unroll
        for (int nt = 0; nt < 8; ++nt)
#pragma unroll
            for (int c = 0; c < 4; ++c) S[nt][c] = 0.0f;

#pragma unroll
        for (int kt = 0; kt < 8; ++kt) {
            const int kc = kt * 8;
            uint32_t a[4];
            {
                int r = (w16 + grp) * QS_ST + kc + lq;
                a[0] = Qs[r];
                a[1] = Qs[r + 8 * QS_ST];
                a[2] = Qs[r + 4];
                a[3] = Qs[r + 8 * QS_ST + 4];
            }
#pragma unroll
            for (int nt = 0; nt < 8; ++nt) {
                uint32_t b[2];
                int o = (nt * 8 + grp) * KS_ST + kc + lq;
                b[0] = KsC[o];
                b[1] = KsC[o + 4];
                mma_tf32(S[nt], a, b);
            }
        }

        if (kb >= 2 * qt) {
#pragma unroll
            for (int nt = 0; nt < 8; ++nt)
#pragma unroll
                for (int c = 0; c < 4; ++c) {
                    int qi = qrow0 + w16 + grp + ((c >> 1) << 3);
                    int kj = kb * 64 + nt * 8 + 2 * lq + (c & 1);
                    if (kj > qi) S[nt][c] = -10000.0f;
                }
        }

#pragma unroll
        for (int nt = 0; nt < 8; ++nt) {
            float p0 = __expf(S[nt][0]);
            float p1 = __expf(S[nt][1]);
            float p2 = __expf(S[nt][2]);
            float p3 = __expf(S[nt][3]);
            l_s[0] += p0 + p1;
            l_s[1] += p2 + p3;
            S[nt][0] = __uint_as_float(f2tf32(p0));
            S[nt][1] = __uint_as_float(f2tf32(p1));
            S[nt][2] = __uint_as_float(f2tf32(p2));
            S[nt][3] = __uint_as_float(f2tf32(p3));
        }

        const int src_a = (lane & 28) | (lq >> 1);
        const int src_b = src_a | 2;
        const bool hi = lq & 1;
#pragma unroll
        for (int kt = 0; kt < 8; ++kt) {
            uint32_t a[4];
            {
                float v0 = __shfl_sync(0xffffffffu, S[kt][0], src_a);
                float v1 = __shfl_sync(0xffffffffu, S[kt][1], src_a);
                float v2 = __shfl_sync(0xffffffffu, S[kt][2], src_a);
                float v3 = __shfl_sync(0xffffffffu, S[kt][3], src_a);
                float w0 = __shfl_sync(0xffffffffu, S[kt][0], src_b);
                float w1 = __shfl_sync(0xffffffffu, S[kt][1], src_b);
                float w2 = __shfl_sync(0xffffffffu, S[kt][2], src_b);
                float w3 = __shfl_sync(0xffffffffu, S[kt][3], src_b);
                a[0] = __float_as_uint(hi ? v1 : v0);
                a[1] = __float_as_uint(hi ? v3 : v2);
                a[2] = __float_as_uint(hi ? w1 : w0);
                a[3] = __float_as_uint(hi ? w3 : w2);
            }
            const int kc = kt * 8;
#pragma unroll
            for (int nt = 0; nt < 8; ++nt) {
                uint32_t b[2];
                b[0] = VsC[(kc + lq) * VS_ST + nt * 8 + grp];
                b[1] = VsC[(kc + lq + 4) * VS_ST + nt * 8 + grp];
                mma_tf32(Oa[nt], a, b);
            }
        }
    }

    l_s[0] += __shfl_xor_sync(0xffffffffu, l_s[0], 1);
    l_s[0] += __shfl_xor_sync(0xffffffffu, l_s[0], 2);
    l_s[1] += __shfl_xor_sync(0xffffffffu, l_s[1], 1);
    l_s[1] += __shfl_xor_sync(0xffffffffu, l_s[1], 2);
    const float inv0 = 1.0f / l_s[0];
    const float inv1 = 1.0f / l_s[1];
    {
        size_t row = (size_t)(qrow0 + w16 + grp);
#pragma unroll
        for (int nt = 0; nt < 8; ++nt) {
            int col = col0 + nt * 8 + 2 * lq;
            *(float2*)&O[row * DM + col] =
                make_float2(Oa[nt][0] * inv0, Oa[nt][1] * inv0);
            *(float2*)&O[(row + 8) * DM + col] =
                make_float2(Oa[nt][2] * inv1, Oa[nt][3] * inv1);
        }
    }
}

// ---------------------------------------------------------------------------
extern "C" void kernel_launch(void* const* d_in, const int* in_sizes, int n_in,
                              void* d_out, int out_size) {
    const float* x  = (const float*)d_in[0];
    const float* wq = (const float*)d_in[1];
    const float* wk = (const float*)d_in[2];
    const float* wv = (const float*)d_in[3];
    const float* wo = (const float*)d_in[4];
    float* out = (float*)d_out;

    float *q, *k, *v, *ctx;
    cudaGetSymbolAddress((void**)&q,   g_q);
    cudaGetSymbolAddress((void**)&k,   g_k);
    cudaGetSymbolAddress((void**)&v,   g_v);
    cudaGetSymbolAddress((void**)&ctx, g_ctx);

    cudaFuncSetAttribute(attn_mma, cudaFuncAttributeMaxDynamicSharedMemorySize,
                         ATT_SMEM_BYTES);

    // Fused QKV projection: one launch, z selects weight/output.
    dim3 qkv_grid(DM / 128, SEQ / 128, 3);
    gemm_tf32_db<SEQ, DM, DM, true><<<qkv_grid, 256>>>(
        x, wq, wk, wv, q, k, v, 0.125f);

    attn_mma<<<dim3(SEQ / 128, NH), 256, ATT_SMEM_BYTES>>>(q, k, v, ctx);

    dim3 wo_grid(DM / 128, SEQ / 128, 1);
    gemm_tf32_db<SEQ, DM, DM, false><<<wo_grid, 256>>>(
        ctx, wo, wo, wo, out, out, out, 1.0f);
}

// round 7
// speedup vs baseline: 2.6180x; 1.0045x over previous
#include <cuda_runtime.h>
#include <cstdint>

static constexpr int SEQ = 4096;
static constexpr int DM  = 1024;
static constexpr int NH  = 16;
static constexpr int HD  = 64;

// Q scale with log2(e) folded: attention uses exp2 instead of exp.
#define QSCALE 0.18033688011112042f  // 0.125 * log2(e)

// Scratch (allocation-free rule: device globals)
__device__ float    g_q[SEQ * DM];     // tf32 bits
__device__ float    g_k[SEQ * DM];     // tf32 bits
__device__ float    g_v[SEQ * DM];     // tf32 bits
__device__ float    g_ctx[SEQ * DM];   // tf32 bits
__device__ uint32_t g_xc[SEQ * DM];    // x  converted to tf32 bits
__device__ uint32_t g_wqc[DM * DM];
__device__ uint32_t g_wkc[DM * DM];
__device__ uint32_t g_wvc[DM * DM];
__device__ uint32_t g_woc[DM * DM];

__device__ __forceinline__ uint32_t f2tf32(float f) {
    uint32_t u;
    asm("cvt.rna.tf32.f32 %0, %1;" : "=r"(u) : "f"(f));
    return u;
}

__device__ __forceinline__ float ex2f(float x) {
    float y;
    asm("ex2.approx.f32 %0, %1;" : "=f"(y) : "f"(x));
    return y;
}

__device__ __forceinline__ void mma_tf32(float* d, const uint32_t* a, const uint32_t* b) {
    asm volatile(
        "mma.sync.aligned.m16n8k8.row.col.f32.tf32.tf32.f32 "
        "{%0,%1,%2,%3}, {%4,%5,%6,%7}, {%8,%9}, {%0,%1,%2,%3};"
        : "+f"(d[0]), "+f"(d[1]), "+f"(d[2]), "+f"(d[3])
        : "r"(a[0]), "r"(a[1]), "r"(a[2]), "r"(a[3]), "r"(b[0]), "r"(b[1]));
}

__device__ __forceinline__ uint32_t smem_u32(const void* p) {
    uint32_t a;
    asm("{ .reg .u64 t; cvta.to.shared.u64 t, %1; cvt.u32.u64 %0, t; }"
        : "=r"(a) : "l"(p));
    return a;
}

__device__ __forceinline__ void cp16(uint32_t dst, const void* src) {
    asm volatile("cp.async.cg.shared.global [%0], [%1], 16;" :: "r"(dst), "l"(src));
}
#define CP_COMMIT() asm volatile("cp.async.commit_group;" ::: "memory")
#define CP_WAIT0()  asm volatile("cp.async.wait_group 0;" ::: "memory")
#define CP_WAIT1()  asm volatile("cp.async.wait_group 1;" ::: "memory")

// ---------------------------------------------------------------------------
// Prep: convert x and the four weights to tf32 bits (rna), once per launch.
// grid (1024, 1, 8), block 256. Each z-slice converts 1M floats (x = 4 slices).
// ---------------------------------------------------------------------------
__global__ void __launch_bounds__(256) cvt_prep(const float* __restrict__ x,
                                                const float* __restrict__ wq,
                                                const float* __restrict__ wk,
                                                const float* __restrict__ wv,
                                                const float* __restrict__ wo) {
    const int z = blockIdx.z;
    const int idx = blockIdx.x * 256 + threadIdx.x;  // 0..262143 per segment
    constexpr int MSEG = 1024 * 1024;
    const float* src;
    uint32_t* dst;
    if (z < 4)       { src = x + z * MSEG; dst = g_xc + z * MSEG; }
    else if (z == 4) { src = wq; dst = g_wqc; }
    else if (z == 5) { src = wk; dst = g_wkc; }
    else if (z == 6) { src = wv; dst = g_wvc; }
    else             { src = wo; dst = g_woc; }
    float4 v = ((const float4*)src)[idx];
    ((uint4*)dst)[idx] = make_uint4(f2tf32(v.x), f2tf32(v.y), f2tf32(v.z), f2tf32(v.w));
}

// ---------------------------------------------------------------------------
// TF32 GEMM (NT) on pre-converted tf32-bit operands.
// C[m,n] = sum_k A[m,k]*B[n,k].  BM=256, BN=128, BK=16.
// 8 warps as 4(M) x 2(N), warp tile 64x64 (im=4, in=8): 1.0 LDS/MMA.
// 3-stage cp.async pipeline, one barrier per k-iteration. 90 KB dynamic smem.
// CVT_OUT: epilogue emits tf32-rounded bits (scale folded).
// ---------------------------------------------------------------------------
static constexpr int G_BM = 256, G_BN = 128, G_BK = 16, G_PAD = 20;
static constexpr int G_STA = G_BM * G_PAD;           // 5120 words
static constexpr int G_STB = G_BN * G_PAD;           // 2560 words
static constexpr int G_STG = G_STA + G_STB;          // 7680 words per stage
static constexpr int G_SMEM_BYTES = 3 * G_STG * 4;   // 92160 bytes
static constexpr int G_NIT = DM / G_BK;              // 64

template <bool CVT_OUT>
__global__ void __launch_bounds__(256, 1)
gemm_tf32_big(const uint32_t* __restrict__ A,
              const uint32_t* __restrict__ B0, const uint32_t* __restrict__ B1,
              const uint32_t* __restrict__ B2,
              float* __restrict__ C0, float* __restrict__ C1, float* __restrict__ C2,
              float scale0) {
    extern __shared__ uint32_t smg[];

    const uint32_t* B = (blockIdx.z == 0) ? B0 : (blockIdx.z == 1 ? B1 : B2);
    float*          C = (blockIdx.z == 0) ? C0 : (blockIdx.z == 1 ? C1 : C2);
    const float oscale = (blockIdx.z == 0) ? scale0 : 1.0f;

    const int tid  = threadIdx.x;
    const int warp = tid >> 5;
    const int lane = tid & 31;
    const int grp  = lane >> 2;
    const int lq   = lane & 3;
    const int wm0  = (warp >> 1) * 64;   // 4 m-warps
    const int wn0  = (warp & 1) * 64;    // 2 n-warps

    const int bm = blockIdx.y * G_BM;
    const int bn = blockIdx.x * G_BN;

    // staging: A row per thread (256 rows), B row per 2 threads (128 rows)
    const uint32_t* Ag = A + (size_t)(bm + tid) * DM;
    const uint32_t* Bg = B + (size_t)(bn + (tid >> 1)) * DM + (tid & 1) * 8;
    const uint32_t a_sm = smem_u32(smg) + (uint32_t)(tid * G_PAD) * 4;
    const uint32_t b_sm = smem_u32(smg) +
        (uint32_t)(G_STA + (tid >> 1) * G_PAD + (tid & 1) * 8) * 4;

#define G_ISSUE(it, stg)                                                      \
    do {                                                                      \
        const uint32_t* ap = Ag + (it) * G_BK;                                \
        const uint32_t* bp = Bg + (it) * G_BK;                                \
        uint32_t ao = a_sm + (uint32_t)(stg) * G_STG * 4;                     \
        uint32_t bo = b_sm + (uint32_t)(stg) * G_STG * 4;                     \
        cp16(ao, ap); cp16(ao + 16, ap + 4);                                  \
        cp16(ao + 32, ap + 8); cp16(ao + 48, ap + 12);                        \
        cp16(bo, bp); cp16(bo + 16, bp + 4);                                  \
        CP_COMMIT();                                                          \
    } while (0)

    G_ISSUE(0, 0);
    G_ISSUE(1, 1);

    float acc[4][8][4] = {};

#pragma unroll 1
    for (int i = 0; i < G_NIT; ++i) {
        if (i == G_NIT - 1) { CP_WAIT0(); } else { CP_WAIT1(); }
        __syncthreads();
        if (i + 2 < G_NIT) G_ISSUE(i + 2, (i + 2) % 3);

        const uint32_t* As = smg + (i % 3) * G_STG;
        const uint32_t* Bs = As + G_STA;

#pragma unroll
        for (int ks = 0; ks < G_BK; ks += 8) {
            uint32_t afr[4][4];
            uint32_t bfr[8][2];
#pragma unroll
            for (int im = 0; im < 4; ++im) {
                int r0 = (wm0 + im * 16 + grp) * G_PAD + ks + lq;
                afr[im][0] = As[r0];
                afr[im][1] = As[r0 + 8 * G_PAD];
                afr[im][2] = As[r0 + 4];
                afr[im][3] = As[r0 + 8 * G_PAD + 4];
            }
#pragma unroll
            for (int in = 0; in < 8; ++in) {
                int c0 = (wn0 + in * 8 + grp) * G_PAD + ks + lq;
                bfr[in][0] = Bs[c0];
                bfr[in][1] = Bs[c0 + 4];
            }
#pragma unroll
            for (int im = 0; im < 4; ++im)
#pragma unroll
                for (int in = 0; in < 8; ++in)
                    mma_tf32(acc[im][in], afr[im], bfr[in]);
        }
    }
#undef G_ISSUE

#pragma unroll
    for (int im = 0; im < 4; ++im) {
#pragma unroll
        for (int in = 0; in < 8; ++in) {
            size_t row0 = (size_t)(bm + wm0 + im * 16 + grp);
            int col = bn + wn0 + in * 8 + 2 * lq;
            float o0 = acc[im][in][0], o1 = acc[im][in][1];
            float o2 = acc[im][in][2], o3 = acc[im][in][3];
            if (CVT_OUT) {
                o0 = __uint_as_float(f2tf32(o0 * oscale));
                o1 = __uint_as_float(f2tf32(o1 * oscale));
                o2 = __uint_as_float(f2tf32(o2 * oscale));
                o3 = __uint_as_float(f2tf32(o3 * oscale));
            }
            *(float2*)&C[row0 * DM + col]       = make_float2(o0, o1);
            *(float2*)&C[(row0 + 8) * DM + col] = make_float2(o2, o3);
        }
    }
}

// ---------------------------------------------------------------------------
// Flash attention, TF32 MMA, no-max base-2 softmax (log2e folded into Q),
// cp.async double-buffered K/V, P in registers via shuffle permute.
// Epilogue writes ctx as tf32 bits (feeds WO GEMM cp.async path).
// ---------------------------------------------------------------------------
static constexpr int QS_ST = 68;
static constexpr int KS_ST = 68;
static constexpr int VS_ST = 72;
static constexpr int ATT_SMEM_WORDS = 128 * QS_ST + 2 * 64 * KS_ST + 2 * 64 * VS_ST;
static constexpr int ATT_SMEM_BYTES = ATT_SMEM_WORDS * 4;

__global__ void __launch_bounds__(256, 2) attn_mma(const float* __restrict__ Q,
                                                   const float* __restrict__ K,
                                                   const float* __restrict__ V,
                                                   float* __restrict__ O) {
    extern __shared__ uint32_t sm[];
    uint32_t* Qs = sm;                         // [128][68]
    uint32_t* Ks = Qs + 128 * QS_ST;           // [2][64][68]
    uint32_t* Vs = Ks + 2 * 64 * KS_ST;        // [2][64][72]

    const int tid  = threadIdx.x;
    const int lane = tid & 31;
    const int grp  = lane >> 2;
    const int lq   = lane & 3;
    const int head = blockIdx.y;
    const int qt   = (int)gridDim.x - 1 - (int)blockIdx.x;  // long CTAs first
    const int qrow0 = qt * 128;
    const int col0  = head * HD;
    const int w16   = (tid >> 5) * 16;

    const int krow = tid >> 2;
    const int kf0  = (tid & 3) * 16;
    const float* Ksrc = K + (size_t)krow * DM + col0 + kf0;
    const float* Vsrc = V + (size_t)krow * DM + col0 + kf0;
    const uint32_t ksd = smem_u32(Ks) + (uint32_t)(krow * KS_ST + kf0) * 4;
    const uint32_t vsd = smem_u32(Vs) + (uint32_t)(krow * VS_ST + kf0) * 4;

    {
        int qrow = tid >> 1;
        int qf0  = (tid & 1) * 32;
        const float* qsrc = Q + (size_t)(qrow0 + qrow) * DM + col0 + qf0;
        uint32_t qdst = smem_u32(Qs) + (uint32_t)(qrow * QS_ST + qf0) * 4;
#pragma unroll
        for (int p = 0; p < 8; ++p) cp16(qdst + p * 16, qsrc + p * 4);
#pragma unroll
        for (int p = 0; p < 4; ++p) {
            cp16(ksd + p * 16, Ksrc + p * 4);
            cp16(vsd + p * 16, Vsrc + p * 4);
        }
        CP_COMMIT();
    }

    float Oa[8][4];
    float l_s[2] = {0.0f, 0.0f};
#pragma unroll
    for (int nt = 0; nt < 8; ++nt)
#pragma unroll
        for (int c = 0; c < 4; ++c) Oa[nt][c] = 0.0f;

    const int nkb = 2 * qt + 2;
    for (int kb = 0; kb < nkb; ++kb) {
        CP_WAIT0();
        __syncthreads();

        if (kb + 1 < nkb) {
            const int b = (kb + 1) & 1;
            const float* Kp = Ksrc + (size_t)(kb + 1) * 64 * DM;
            const float* Vp = Vsrc + (size_t)(kb + 1) * 64 * DM;
            const uint32_t kd = ksd + (uint32_t)(b * 64 * KS_ST) * 4;
            const uint32_t vd = vsd + (uint32_t)(b * 64 * VS_ST) * 4;
#pragma unroll
            for (int p = 0; p < 4; ++p) {
                cp16(kd + p * 16, Kp + p * 4);
                cp16(vd + p * 16, Vp + p * 4);
            }
            CP_COMMIT();
        }

        const uint32_t* KsC = Ks + (kb & 1) * 64 * KS_ST;
        const uint32_t* VsC = Vs + (kb & 1) * 64 * VS_ST;

        float S[8][4];
#pragma unroll
        for (int nt = 0; nt < 8; ++nt)
#pragma unroll
            for (int c = 0; c < 4; ++c) S[nt][c] = 0.0f;

#pragma unroll
        for (int kt = 0; kt < 8; ++kt) {
            const int kc = kt * 8;
            uint32_t a[4];
            {
                int r = (w16 + grp) * QS_ST + kc + lq;
                a[0] = Qs[r];
                a[1] = Qs[r + 8 * QS_ST];
                a[2] = Qs[r + 4];
                a[3] = Qs[r + 8 * QS_ST + 4];
            }
#pragma unroll
            for (int nt = 0; nt < 8; ++nt) {
                uint32_t b[2];
                int o = (nt * 8 + grp) * KS_ST + kc + lq;
                b[0] = KsC[o];
                b[1] = KsC[o + 4];
                mma_tf32(S[nt], a, b);
            }
        }

        if (kb >= 2 * qt) {
#pragma unroll
            for (int nt = 0; nt < 8; ++nt)
#pragma unroll
                for (int c = 0; c < 4; ++c) {
                    int qi = qrow0 + w16 + grp + ((c >> 1) << 3);
                    int kj = kb * 64 + nt * 8 + 2 * lq + (c & 1);
                    if (kj > qi) S[nt][c] = -10000.0f;
                }
        }

        // p = 2^s  (log2e folded into Q); masked -> 2^-10000 = 0
#pragma unroll
        for (int nt = 0; nt < 8; ++nt) {
            float p0 = ex2f(S[nt][0]);
            float p1 = ex2f(S[nt][1]);
            float p2 = ex2f(S[nt][2]);
            float p3 = ex2f(S[nt][3]);
            l_s[0] += p0 + p1;
            l_s[1] += p2 + p3;
            S[nt][0] = __uint_as_float(f2tf32(p0));
            S[nt][1] = __uint_as_float(f2tf32(p1));
            S[nt][2] = __uint_as_float(f2tf32(p2));
            S[nt][3] = __uint_as_float(f2tf32(p3));
        }

        const int src_a = (lane & 28) | (lq >> 1);
        const int src_b = src_a | 2;
        const bool hi = lq & 1;
#pragma unroll
        for (int kt = 0; kt < 8; ++kt) {
            uint32_t a[4];
            {
                float v0 = __shfl_sync(0xffffffffu, S[kt][0], src_a);
                float v1 = __shfl_sync(0xffffffffu, S[kt][1], src_a);
                float v2 = __shfl_sync(0xffffffffu, S[kt][2], src_a);
                float v3 = __shfl_sync(0xffffffffu, S[kt][3], src_a);
                float w0 = __shfl_sync(0xffffffffu, S[kt][0], src_b);
                float w1 = __shfl_sync(0xffffffffu, S[kt][1], src_b);
                float w2 = __shfl_sync(0xffffffffu, S[kt][2], src_b);
                float w3 = __shfl_sync(0xffffffffu, S[kt][3], src_b);
                a[0] = __float_as_uint(hi ? v1 : v0);
                a[1] = __float_as_uint(hi ? v3 : v2);
                a[2] = __float_as_uint(hi ? w1 : w0);
                a[3] = __float_as_uint(hi ? w3 : w2);
            }
            const int kc = kt * 8;
#pragma unroll
            for (int nt = 0; nt < 8; ++nt) {
                uint32_t b[2];
                b[0] = VsC[(kc + lq) * VS_ST + nt * 8 + grp];
                b[1] = VsC[(kc + lq + 4) * VS_ST + nt * 8 + grp];
                mma_tf32(Oa[nt], a, b);
            }
        }
    }

    l_s[0] += __shfl_xor_sync(0xffffffffu, l_s[0], 1);
    l_s[0] += __shfl_xor_sync(0xffffffffu, l_s[0], 2);
    l_s[1] += __shfl_xor_sync(0xffffffffu, l_s[1], 1);
    l_s[1] += __shfl_xor_sync(0xffffffffu, l_s[1], 2);
    const float inv0 = 1.0f / l_s[0];
    const float inv1 = 1.0f / l_s[1];
    {
        size_t row = (size_t)(qrow0 + w16 + grp);
#pragma unroll
        for (int nt = 0; nt < 8; ++nt) {
            int col = col0 + nt * 8 + 2 * lq;
            // write tf32 bits: ctx feeds the WO GEMM's raw cp.async path
            uint2 lo = make_uint2(f2tf32(Oa[nt][0] * inv0), f2tf32(Oa[nt][1] * inv0));
            uint2 hi2 = make_uint2(f2tf32(Oa[nt][2] * inv1), f2tf32(Oa[nt][3] * inv1));
            *(uint2*)&O[row * DM + col]       = lo;
            *(uint2*)&O[(row + 8) * DM + col] = hi2;
        }
    }
}

// ---------------------------------------------------------------------------
extern "C" void kernel_launch(void* const* d_in, const int* in_sizes, int n_in,
                              void* d_out, int out_size) {
    const float* x  = (const float*)d_in[0];
    const float* wq = (const float*)d_in[1];
    const float* wk = (const float*)d_in[2];
    const float* wv = (const float*)d_in[3];
    const float* wo = (const float*)d_in[4];
    float* out = (float*)d_out;

    float *q, *k, *v, *ctx;
    uint32_t *xc, *wqc, *wkc, *wvc, *woc;
    cudaGetSymbolAddress((void**)&q,   g_q);
    cudaGetSymbolAddress((void**)&k,   g_k);
    cudaGetSymbolAddress((void**)&v,   g_v);
    cudaGetSymbolAddress((void**)&ctx, g_ctx);
    cudaGetSymbolAddress((void**)&xc,  g_xc);
    cudaGetSymbolAddress((void**)&wqc, g_wqc);
    cudaGetSymbolAddress((void**)&wkc, g_wkc);
    cudaGetSymbolAddress((void**)&wvc, g_wvc);
    cudaGetSymbolAddress((void**)&woc, g_woc);

    cudaFuncSetAttribute(attn_mma, cudaFuncAttributeMaxDynamicSharedMemorySize,
                         ATT_SMEM_BYTES);
    cudaFuncSetAttribute(gemm_tf32_big<true>,
                         cudaFuncAttributeMaxDynamicSharedMemorySize, G_SMEM_BYTES);
    cudaFuncSetAttribute(gemm_tf32_big<false>,
                         cudaFuncAttributeMaxDynamicSharedMemorySize, G_SMEM_BYTES);

    // 1) convert x + weights to tf32 bits
    cvt_prep<<<dim3(1024, 1, 8), 256>>>(x, wq, wk, wv, wo);

    // 2) fused QKV projection (z selects weight/output)
    dim3 qkv_grid(DM / G_BN, SEQ / G_BM, 3);
    gemm_tf32_big<true><<<qkv_grid, 256, G_SMEM_BYTES>>>(
        xc, wqc, wkc, wvc, q, k, v, QSCALE);

    // 3) attention (writes tf32-bit ctx)
    attn_mma<<<dim3(SEQ / 128, NH), 256, ATT_SMEM_BYTES>>>(q, k, v, ctx);

    // 4) output projection (plain fp32 result)
    dim3 wo_grid(DM / G_BN, SEQ / G_BM, 1);
    gemm_tf32_big<false><<<wo_grid, 256, G_SMEM_BYTES>>>(
        (const uint32_t*)ctx, woc, woc, woc, out, out, out, 1.0f);
}

// round 8
// speedup vs baseline: 6.2019x; 2.3689x over previous
#include <cuda_runtime.h>
#include <cuda_fp16.h>
#include <cstdint>

static constexpr int SEQ = 4096;
static constexpr int DM  = 1024;
static constexpr int NH  = 16;
static constexpr int HD  = 64;

// Q scale with log2(e) folded: attention uses exp2.
#define QSCALE 0.18033688011112042f  // 0.125 * log2(e)

// Scratch (allocation-free rule: device globals). All fp16.
__device__ __half g_q[SEQ * DM];
__device__ __half g_k[SEQ * DM];
__device__ __half g_v[SEQ * DM];
__device__ __half g_ctx[SEQ * DM];
__device__ __half g_xh[SEQ * DM];
__device__ __half g_wqh[DM * DM];
__device__ __half g_wkh[DM * DM];
__device__ __half g_wvh[DM * DM];
__device__ __half g_woh[DM * DM];

__device__ __forceinline__ float ex2f(float x) {
    float y;
    asm("ex2.approx.f32 %0, %1;" : "=f"(y) : "f"(x));
    return y;
}

__device__ __forceinline__ uint32_t h2u(__half2 h) { return *(uint32_t*)&h; }

__device__ __forceinline__ void mma_f16(float* d, const uint32_t* a, const uint32_t* b) {
    asm volatile(
        "mma.sync.aligned.m16n8k16.row.col.f32.f16.f16.f32 "
        "{%0,%1,%2,%3}, {%4,%5,%6,%7}, {%8,%9}, {%0,%1,%2,%3};"
        : "+f"(d[0]), "+f"(d[1]), "+f"(d[2]), "+f"(d[3])
        : "r"(a[0]), "r"(a[1]), "r"(a[2]), "r"(a[3]), "r"(b[0]), "r"(b[1]));
}

__device__ __forceinline__ uint32_t smem_u32(const void* p) {
    uint32_t a;
    asm("{ .reg .u64 t; cvta.to.shared.u64 t, %1; cvt.u32.u64 %0, t; }"
        : "=r"(a) : "l"(p));
    return a;
}

__device__ __forceinline__ void ldsm_x4(uint32_t* r, uint32_t addr) {
    asm volatile("ldmatrix.sync.aligned.m8n8.x4.shared.b16 {%0,%1,%2,%3}, [%4];"
                 : "=r"(r[0]), "=r"(r[1]), "=r"(r[2]), "=r"(r[3]) : "r"(addr));
}
__device__ __forceinline__ void ldsm_x2(uint32_t* r, uint32_t addr) {
    asm volatile("ldmatrix.sync.aligned.m8n8.x2.shared.b16 {%0,%1}, [%2];"
                 : "=r"(r[0]), "=r"(r[1]) : "r"(addr));
}
__device__ __forceinline__ void ldsm_x2t(uint32_t* r, uint32_t addr) {
    asm volatile("ldmatrix.sync.aligned.m8n8.x2.trans.shared.b16 {%0,%1}, [%2];"
                 : "=r"(r[0]), "=r"(r[1]) : "r"(addr));
}

__device__ __forceinline__ void cp16(uint32_t dst, const void* src) {
    asm volatile("cp.async.cg.shared.global [%0], [%1], 16;" :: "r"(dst), "l"(src));
}
#define CP_COMMIT() asm volatile("cp.async.commit_group;" ::: "memory")
#define CP_WAIT0()  asm volatile("cp.async.wait_group 0;" ::: "memory")
#define CP_WAIT1()  asm volatile("cp.async.wait_group 1;" ::: "memory")

// ---------------------------------------------------------------------------
// Prep: fp32 -> fp16 (rn) for x and the four weights.
// grid (1024,1,8) x 256: z 0-3 = x (1M floats each), z 4-7 = weights.
// ---------------------------------------------------------------------------
__global__ void __launch_bounds__(256) cvt_prep(const float* __restrict__ x,
                                                const float* __restrict__ wq,
                                                const float* __restrict__ wk,
                                                const float* __restrict__ wv,
                                                const float* __restrict__ wo) {
    const int z = blockIdx.z;
    const int idx = blockIdx.x * 256 + threadIdx.x;  // 0..262143
    constexpr int MSEG = 1024 * 1024;
    const float* src;
    __half* dst;
    if (z < 4)       { src = x + (size_t)z * MSEG; dst = g_xh + (size_t)z * MSEG; }
    else if (z == 4) { src = wq; dst = g_wqh; }
    else if (z == 5) { src = wk; dst = g_wkh; }
    else if (z == 6) { src = wv; dst = g_wvh; }
    else             { src = wo; dst = g_woh; }
    float4 v = ((const float4*)src)[idx];
    __half2 h0 = __floats2half2_rn(v.x, v.y);
    __half2 h1 = __floats2half2_rn(v.z, v.w);
    ((uint2*)dst)[idx] = make_uint2(h2u(h0), h2u(h1));
}

// ---------------------------------------------------------------------------
// FP16 GEMM (NT): C[m,n] = sum_k A[m,k]*B[n,k], fp32 accumulate.
// BM=BN=128, BK=32 halves, 8 warps 2(M)x4(N), warp 64x32.
// 3-stage cp.async, one barrier/iter. ldmatrix fragment loads.
// Row stride 20 words (16 data + 4 pad): all ldmatrix phases conflict-free.
// ---------------------------------------------------------------------------
static constexpr int G_ST   = 20;                   // words per row
static constexpr int G_STA  = 128 * G_ST;           // 2560 words
static constexpr int G_STG  = 2 * G_STA;            // 5120 words per stage
static constexpr int G_SMEM = 3 * G_STG * 4;        // 61440 bytes
static constexpr int G_NIT  = DM / 32;              // 32

template <bool CVT_OUT>
__global__ void __launch_bounds__(256, 2)
gemm_f16(const __half* __restrict__ A,
         const __half* __restrict__ B0, const __half* __restrict__ B1,
         const __half* __restrict__ B2,
         void* __restrict__ C0, void* __restrict__ C1, void* __restrict__ C2,
         float scale0) {
    extern __shared__ uint32_t smg[];

    const __half* B = (blockIdx.z == 0) ? B0 : (blockIdx.z == 1 ? B1 : B2);
    void*         C = (blockIdx.z == 0) ? C0 : (blockIdx.z == 1 ? C1 : C2);
    const float oscale = (blockIdx.z == 0) ? scale0 : 1.0f;

    const int tid  = threadIdx.x;
    const int warp = tid >> 5;
    const int lane = tid & 31;
    const int grp  = lane >> 2;
    const int lq   = lane & 3;
    const int ln16 = lane & 15;
    const int hi16 = lane >> 4;          // 0/1
    const int ln8  = lane & 7;
    const int bhi  = (lane >> 3) & 1;    // 0/1
    const int wm0  = (warp & 1) * 64;    // 2 m-warps
    const int wn0  = (warp >> 1) * 32;   // 4 n-warps

    const int bm = blockIdx.y * 128;
    const int bn = blockIdx.x * 128;

    // staging: thread -> (row tid>>1, 32B half (tid&1))
    const __half* Ag = A + (size_t)(bm + (tid >> 1)) * DM + (tid & 1) * 16;
    const __half* Bg = B + (size_t)(bn + (tid >> 1)) * DM + (tid & 1) * 16;
    const uint32_t smb = smem_u32(smg);
    const uint32_t a_sm = smb + (uint32_t)((tid >> 1) * G_ST + (tid & 1) * 8) * 4;
    const uint32_t b_sm = a_sm + (uint32_t)G_STA * 4;

#define G_ISSUE(it, stg)                                                      \
    do {                                                                      \
        const __half* ap = Ag + (size_t)(it) * 32;                            \
        const __half* bp = Bg + (size_t)(it) * 32;                            \
        uint32_t so = (uint32_t)(stg) * G_STG * 4;                            \
        cp16(a_sm + so, ap); cp16(a_sm + so + 16, ap + 8);                    \
        cp16(b_sm + so, bp); cp16(b_sm + so + 16, bp + 8);                    \
        CP_COMMIT();                                                          \
    } while (0)

    G_ISSUE(0, 0);
    G_ISSUE(1, 1);

    float acc[4][4][4] = {};

#pragma unroll 1
    for (int i = 0; i < G_NIT; ++i) {
        if (i == G_NIT - 1) { CP_WAIT0(); } else { CP_WAIT1(); }
        __syncthreads();
        if (i + 2 < G_NIT) G_ISSUE(i + 2, (i + 2) % 3);

        const uint32_t sA = smb + (uint32_t)(i % 3) * G_STG * 4;
        const uint32_t sB = sA + (uint32_t)G_STA * 4;

#pragma unroll
        for (int s = 0; s < 2; ++s) {
            uint32_t afr[4][4];
#pragma unroll
            for (int im = 0; im < 4; ++im)
                ldsm_x4(afr[im],
                        sA + (uint32_t)((wm0 + im * 16 + ln16) * G_ST + s * 8 + hi16 * 4) * 4);
#pragma unroll
            for (int in = 0; in < 4; ++in) {
                uint32_t bfr[2];
                ldsm_x2(bfr,
                        sB + (uint32_t)((wn0 + in * 8 + ln8) * G_ST + s * 8 + bhi * 4) * 4);
#pragma unroll
                for (int im = 0; im < 4; ++im)
                    mma_f16(acc[im][in], afr[im], bfr);
            }
        }
    }
#undef G_ISSUE

#pragma unroll
    for (int im = 0; im < 4; ++im) {
#pragma unroll
        for (int in = 0; in < 4; ++in) {
            size_t row0 = (size_t)(bm + wm0 + im * 16 + grp);
            int col = bn + wn0 + in * 8 + 2 * lq;
            if (CVT_OUT) {
                __half* Ch = (__half*)C;
                __half2 lo = __floats2half2_rn(acc[im][in][0] * oscale,
                                               acc[im][in][1] * oscale);
                __half2 hi = __floats2half2_rn(acc[im][in][2] * oscale,
                                               acc[im][in][3] * oscale);
                *(uint32_t*)&Ch[row0 * DM + col]       = h2u(lo);
                *(uint32_t*)&Ch[(row0 + 8) * DM + col] = h2u(hi);
            } else {
                float* Cf = (float*)C;
                *(float2*)&Cf[row0 * DM + col] =
                    make_float2(acc[im][in][0], acc[im][in][1]);
                *(float2*)&Cf[(row0 + 8) * DM + col] =
                    make_float2(acc[im][in][2], acc[im][in][3]);
            }
        }
    }
}

// ---------------------------------------------------------------------------
// Flash attention, fp16 MMA m16n8k16. q-tile 128, kv-tile 64, 8 warps x m16.
// No-max base-2 softmax. cp.async double-buffered K/V. V via ldmatrix.trans
// (no transpose store). QK C-fragment == PV A-fragment (no shuffles).
// Smem (halves, row stride 72 = 36 words): Qs[128] | Ks[2][64] | Vs[2][64].
// ---------------------------------------------------------------------------
static constexpr int A_ST   = 36;                       // words per row
static constexpr int A_QW   = 128 * A_ST;               // 4608 words
static constexpr int A_KVW  = 64 * A_ST;                // 2304 words per stage
static constexpr int A_SMEM = (A_QW + 4 * A_KVW) * 4;   // 55296 bytes

__global__ void __launch_bounds__(256, 2) attn_f16(const __half* __restrict__ Q,
                                                   const __half* __restrict__ K,
                                                   const __half* __restrict__ V,
                                                   __half* __restrict__ O) {
    extern __shared__ uint32_t sm[];

    const int tid  = threadIdx.x;
    const int lane = tid & 31;
    const int grp  = lane >> 2;
    const int lq   = lane & 3;
    const int ln16 = lane & 15;
    const int hi16 = lane >> 4;
    const int ln8  = lane & 7;
    const int bhi  = (lane >> 3) & 1;
    const int head = blockIdx.y;
    const int qt   = (int)gridDim.x - 1 - (int)blockIdx.x;  // long CTAs first
    const int qrow0 = qt * 128;
    const int col0  = head * HD;
    const int w16   = (tid >> 5) * 16;

    const uint32_t smb = smem_u32(sm);

    // ---- Prologue: Q tile + K(0),V(0) via cp.async group 0 ----
    {
        int qrow = tid >> 1;
        const __half* qs = Q + (size_t)(qrow0 + qrow) * DM + col0 + (tid & 1) * 32;
        uint32_t qd = smb + (uint32_t)(qrow * A_ST + (tid & 1) * 16) * 4;
#pragma unroll
        for (int p = 0; p < 4; ++p) cp16(qd + p * 16, qs + p * 8);
    }
    const int krow = tid >> 2;
    const int kch  = (tid & 3) * 16;  // halves
    const __half* Ksrc = K + (size_t)krow * DM + col0 + kch;
    const __half* Vsrc = V + (size_t)krow * DM + col0 + kch;
    const uint32_t ksd = smb + (uint32_t)(A_QW + krow * A_ST + (tid & 3) * 8) * 4;
    const uint32_t vsd = smb + (uint32_t)(A_QW + 2 * A_KVW + krow * A_ST + (tid & 3) * 8) * 4;
    {
        cp16(ksd, Ksrc); cp16(ksd + 16, Ksrc + 8);
        cp16(vsd, Vsrc); cp16(vsd + 16, Vsrc + 8);
        CP_COMMIT();
    }

    float Oa[8][4];
    float l_s[2] = {0.0f, 0.0f};
#pragma unroll
    for (int nt = 0; nt < 8; ++nt)
#pragma unroll
        for (int c = 0; c < 4; ++c) Oa[nt][c] = 0.0f;

    const int nkb = 2 * qt + 2;
    for (int kb = 0; kb < nkb; ++kb) {
        CP_WAIT0();
        __syncthreads();

        if (kb + 1 < nkb) {
            const int b = (kb + 1) & 1;
            const __half* Kp = Ksrc + (size_t)(kb + 1) * 64 * DM;
            const __half* Vp = Vsrc + (size_t)(kb + 1) * 64 * DM;
            const uint32_t kd = ksd + (uint32_t)(b * A_KVW) * 4;
            const uint32_t vd = vsd + (uint32_t)(b * A_KVW) * 4;
            cp16(kd, Kp); cp16(kd + 16, Kp + 8);
            cp16(vd, Vp); cp16(vd + 16, Vp + 8);
            CP_COMMIT();
        }

        const uint32_t sK = smb + (uint32_t)(A_QW + (kb & 1) * A_KVW) * 4;
        const uint32_t sV = smb + (uint32_t)(A_QW + (2 + (kb & 1)) * A_KVW) * 4;

        // ---- S = Q K^T : 4 ktiles x 8 ntiles ----
        float S[8][4];
#pragma unroll
        for (int nt = 0; nt < 8; ++nt)
#pragma unroll
            for (int c = 0; c < 4; ++c) S[nt][c] = 0.0f;

#pragma unroll
        for (int kt = 0; kt < 4; ++kt) {
            uint32_t a[4];
            ldsm_x4(a, smb + (uint32_t)((w16 + ln16) * A_ST + kt * 8 + hi16 * 4) * 4);
#pragma unroll
            for (int nt = 0; nt < 8; ++nt) {
                uint32_t b[2];
                ldsm_x2(b, sK + (uint32_t)((nt * 8 + ln8) * A_ST + kt * 8 + bhi * 4) * 4);
                mma_f16(S[nt], a, b);
            }
        }

        // ---- Causal mask ----
        if (kb >= 2 * qt) {
#pragma unroll
            for (int nt = 0; nt < 8; ++nt)
#pragma unroll
                for (int c = 0; c < 4; ++c) {
                    int qi = qrow0 + w16 + grp + ((c >> 1) << 3);
                    int kj = kb * 64 + nt * 8 + 2 * lq + (c & 1);
                    if (kj > qi) S[nt][c] = -10000.0f;
                }
        }

        // ---- p = 2^s (log2e folded into Q); accumulate l ----
#pragma unroll
        for (int nt = 0; nt < 8; ++nt) {
            float p0 = ex2f(S[nt][0]);
            float p1 = ex2f(S[nt][1]);
            float p2 = ex2f(S[nt][2]);
            float p3 = ex2f(S[nt][3]);
            l_s[0] += p0 + p1;
            l_s[1] += p2 + p3;
            S[nt][0] = p0; S[nt][1] = p1; S[nt][2] = p2; S[nt][3] = p3;
        }

        // ---- O += P V : C-frag == A-frag (pack half2), V via ldmatrix.trans ----
#pragma unroll
        for (int kt = 0; kt < 4; ++kt) {
            uint32_t a[4];
            a[0] = h2u(__floats2half2_rn(S[2 * kt][0],     S[2 * kt][1]));
            a[1] = h2u(__floats2half2_rn(S[2 * kt][2],     S[2 * kt][3]));
            a[2] = h2u(__floats2half2_rn(S[2 * kt + 1][0], S[2 * kt + 1][1]));
            a[3] = h2u(__floats2half2_rn(S[2 * kt + 1][2], S[2 * kt + 1][3]));
            const uint32_t rowaddr = sV + (uint32_t)((kt * 16 + ln16) * A_ST) * 4;
#pragma unroll
            for (int nt = 0; nt < 8; ++nt) {
                uint32_t b[2];
                ldsm_x2t(b, rowaddr + nt * 16);
                mma_f16(Oa[nt], a, b);
            }
        }
    }

    // ---- Final l reduction + writeback (half2 -> ctx) ----
    l_s[0] += __shfl_xor_sync(0xffffffffu, l_s[0], 1);
    l_s[0] += __shfl_xor_sync(0xffffffffu, l_s[0], 2);
    l_s[1] += __shfl_xor_sync(0xffffffffu, l_s[1], 1);
    l_s[1] += __shfl_xor_sync(0xffffffffu, l_s[1], 2);
    const float inv0 = 1.0f / l_s[0];
    const float inv1 = 1.0f / l_s[1];
    {
        size_t row = (size_t)(qrow0 + w16 + grp);
#pragma unroll
        for (int nt = 0; nt < 8; ++nt) {
            int col = col0 + nt * 8 + 2 * lq;
            __half2 lo = __floats2half2_rn(Oa[nt][0] * inv0, Oa[nt][1] * inv0);
            __half2 hi = __floats2half2_rn(Oa[nt][2] * inv1, Oa[nt][3] * inv1);
            *(uint32_t*)&O[row * DM + col]       = h2u(lo);
            *(uint32_t*)&O[(row + 8) * DM + col] = h2u(hi);
        }
    }
}

// ---------------------------------------------------------------------------
extern "C" void kernel_launch(void* const* d_in, const int* in_sizes, int n_in,
                              void* d_out, int out_size) {
    const float* x  = (const float*)d_in[0];
    const float* wq = (const float*)d_in[1];
    const float* wk = (const float*)d_in[2];
    const float* wv = (const float*)d_in[3];
    const float* wo = (const float*)d_in[4];
    float* out = (float*)d_out;

    __half *q, *k, *v, *ctx, *xh, *wqh, *wkh, *wvh, *woh;
    cudaGetSymbolAddress((void**)&q,   g_q);
    cudaGetSymbolAddress((void**)&k,   g_k);
    cudaGetSymbolAddress((void**)&v,   g_v);
    cudaGetSymbolAddress((void**)&ctx, g_ctx);
    cudaGetSymbolAddress((void**)&xh,  g_xh);
    cudaGetSymbolAddress((void**)&wqh, g_wqh);
    cudaGetSymbolAddress((void**)&wkh, g_wkh);
    cudaGetSymbolAddress((void**)&wvh, g_wvh);
    cudaGetSymbolAddress((void**)&woh, g_woh);

    cudaFuncSetAttribute(attn_f16, cudaFuncAttributeMaxDynamicSharedMemorySize,
                         A_SMEM);
    cudaFuncSetAttribute(gemm_f16<true>,
                         cudaFuncAttributeMaxDynamicSharedMemorySize, G_SMEM);
    cudaFuncSetAttribute(gemm_f16<false>,
                         cudaFuncAttributeMaxDynamicSharedMemorySize, G_SMEM);

    // 1) fp32 -> fp16 conversion of x + weights
    cvt_prep<<<dim3(1024, 1, 8), 256>>>(x, wq, wk, wv, wo);

    // 2) fused QKV projection
    dim3 qkv_grid(DM / 128, SEQ / 128, 3);
    gemm_f16<true><<<qkv_grid, 256, G_SMEM>>>(xh, wqh, wkh, wvh, q, k, v, QSCALE);

    // 3) attention
    attn_f16<<<dim3(SEQ / 128, NH), 256, A_SMEM>>>(q, k, v, ctx);

    // 4) output projection (fp32 out)
    dim3 wo_grid(DM / 128, SEQ / 128, 1);
    gemm_f16<false><<<wo_grid, 256, G_SMEM>>>(ctx, woh, woh, woh, out, out, out, 1.0f);
}